// round 11
// baseline (speedup 1.0000x reference)
#include <cuda_runtime.h>
#include <cuda_fp16.h>
#include <cstdint>
#include <math.h>

#define NN 50000
#define NE 800000

// fp16 fragment-major strides (32-bit words)
#define ABLK 132  // A block (16r x 16k): 32 lanes x 4 words, pad 128->132
#define BBLK 66   // B block (8n x 16k): 32 lanes x 2 words, pad 64->66
#define PIT 132   // legacy tf32 pitch for final_tc

// ----------------------------- scratch globals -----------------------------
__device__ uint32_t g_qh[NN * 64];  // q rows, fp16 half2 words
__device__ uint32_t g_kh[NN * 64];
__device__ uint32_t g_vh[NN * 64];
__device__ float g_den[NN * 128];
__device__ float g_h[NN * 128];

__device__ uint32_t g_WhQKV[384 * 128];  // packed [Wq|Wk|Wv], fp16 frag-major
__device__ uint32_t g_WhEM2[128 * 128];  // channel-permuted [We|Wm], LDSM row order
__device__ uint32_t g_WtF1[128 * 128];   // tf32 [n][k] for final_tc
__device__ uint32_t g_WtF2g[128 * 128];
__device__ float g_vb[128];
__device__ float g_vg[128];

// ----------------------------- helpers -------------------------------------
__device__ __forceinline__ uint32_t rna(float x) {
    uint32_t r;
    asm("cvt.rna.tf32.f32 %0, %1;" : "=r"(r) : "f"(x));
    return r;
}
__device__ __forceinline__ uint32_t pk2(float a, float b) {
    __half2 h = __floats2half2_rn(a, b);
    return *reinterpret_cast<uint32_t*>(&h);
}
__device__ __forceinline__ void mma16(float* c, const uint32_t* a, const uint32_t* b) {
    asm volatile(
        "mma.sync.aligned.m16n8k16.row.col.f32.f16.f16.f32 "
        "{%0,%1,%2,%3}, {%4,%5,%6,%7}, {%8,%9}, {%0,%1,%2,%3};"
        : "+f"(c[0]), "+f"(c[1]), "+f"(c[2]), "+f"(c[3])
        : "r"(a[0]), "r"(a[1]), "r"(a[2]), "r"(a[3]), "r"(b[0]), "r"(b[1]));
}
__device__ __forceinline__ void mma8(float* c, const uint32_t* a, const uint32_t* b) {
    asm volatile(
        "mma.sync.aligned.m16n8k8.row.col.f32.tf32.tf32.f32 "
        "{%0,%1,%2,%3}, {%4,%5,%6,%7}, {%8,%9}, {%0,%1,%2,%3};"
        : "+f"(c[0]), "+f"(c[1]), "+f"(c[2]), "+f"(c[3])
        : "r"(a[0]), "r"(a[1]), "r"(a[2]), "r"(a[3]), "r"(b[0]), "r"(b[1]));
}
__device__ __forceinline__ void ldsm4(uint32_t* r, uint32_t saddr) {
    asm volatile("ldmatrix.sync.aligned.m8n8.x4.shared.b16 {%0,%1,%2,%3}, [%4];"
                 : "=r"(r[0]), "=r"(r[1]), "=r"(r[2]), "=r"(r[3]) : "r"(saddr));
}
__device__ __forceinline__ float mishf(float x) {
    float sp = (x > 20.f) ? x : log1pf(__expf(x));
    return x * tanhf(sp);
}
__device__ __forceinline__ uint64_t mkpol_ef() {
    uint64_t p;
    asm("createpolicy.fractional.L2::evict_first.b64 %0, 1.0;" : "=l"(p));
    return p;
}
__device__ __forceinline__ void cpasync16_ef(uint32_t saddr, const void* g, uint64_t pol) {
    asm volatile("cp.async.cg.shared.global.L2::cache_hint [%0], [%1], 16, %2;"
                 ::"r"(saddr), "l"(g), "l"(pol));
}
#define CP_COMMIT() asm volatile("cp.async.commit_group;" ::: "memory")
#define CP_WAIT0() asm volatile("cp.async.wait_group 0;" ::: "memory")

// fp16 frag-major gmem word index for B value pair (n, k2), k2 = k>>1
__device__ __forceinline__ int fidx16(int n, int k2) {
    return (((n >> 3) << 3) + (k2 >> 3)) * 64 + (((((n & 7) << 2) | (k2 & 3))) << 1) +
           ((k2 >> 2) & 1);
}
// fp16 frag-major smem word index for A halves (r, c), c multiple of 4
__device__ __forceinline__ int aidx16(int r, int c) {
    return ABLK * (((r >> 4) << 3) + (c >> 4)) + ((((r & 7) << 2) | ((c >> 1) & 3)) << 2) +
           ((r >> 3) & 1) + (((c >> 3) & 1) << 1);
}

// ----------------------------- prep kernels --------------------------------
__global__ void prep_T(const float* __restrict__ Wq, const float* __restrict__ Wk,
                       const float* __restrict__ Wv, const float* __restrict__ We,
                       const float* __restrict__ Wm, const float* __restrict__ Wf1,
                       const float* __restrict__ Wf2, const float* __restrict__ gf) {
    int k2 = blockIdx.x, n = threadIdx.x;
    int k0 = k2 * 2, k1 = k0 + 1;
    g_WhQKV[fidx16(n, k2)] = pk2(Wq[k0 * 128 + n], Wq[k1 * 128 + n]);
    g_WhQKV[fidx16(128 + n, k2)] = pk2(Wk[k0 * 128 + n], Wk[k1 * 128 + n]);
    g_WhQKV[fidx16(256 + n, k2)] = pk2(Wv[k0 * 128 + n], Wv[k1 * 128 + n]);
    g_WtF1[n * 128 + k0] = rna(Wf1[k0 * 128 + n]);
    g_WtF1[n * 128 + k1] = rna(Wf1[k1 * 128 + n]);
    g_WtF2g[n * 128 + k0] = rna(gf[k0] * Wf2[k0 * 128 + n]);
    g_WtF2g[n * 128 + k1] = rna(gf[k1] * Wf2[k1 * 128 + n]);
    // EM in LDSM row order. GEMM column j -> channel ch via permutation.
#pragma unroll
    for (int jj = 0; jj < 2; jj++) {
        int j = n + jj * 128;
        int wn = j >> 6, wi = j & 63, nt = wi >> 3, rem = wi & 7, tt = rem >> 1, par = rem & 1;
        int ch = wn * 32 + tt * 8 + nt;
        const float* W = par ? Wm : We;
        int npair = j >> 4, h = (j >> 3) & 1, r = j & 7;
        int ks = k2 >> 3, k8 = (k2 >> 2) & 1, cc = k2 & 3;
        int off = (npair * 8 + ks) * 128 + ((h * 2 + k8) * 8 + r) * 4 + cc;
        g_WhEM2[off] = pk2(W[k0 * 128 + ch], W[k1 * 128 + ch]);
    }
}

__global__ void prep_V(const float* __restrict__ Wf2, const float* __restrict__ bf,
                       const float* __restrict__ gf, const float* __restrict__ bf2) {
    int n = threadIdx.x;
    float a = 0.f, b = 0.f;
    for (int k = 0; k < 128; k++) {
        float w = Wf2[k * 128 + n];
        a = fmaf(bf[k], w, a);
        b = fmaf(gf[k], w, b);
    }
    g_vb[n] = bf2[n] + a;
    g_vg[n] = b;
}

// ----------------------------- fused QKV linear -----------------------------
// q/k/v = NF @ [Wq|Wk|Wv] + b, outputs stored fp16 (half2 words).
__global__ __launch_bounds__(1024, 1) void qkv_tc(
    const float* __restrict__ X,
    const float* __restrict__ bq, const float* __restrict__ bk,
    const float* __restrict__ bv,
    uint32_t* __restrict__ Yq, uint32_t* __restrict__ Yk, uint32_t* __restrict__ Yv) {
    extern __shared__ __align__(16) uint32_t sm[];
    uint32_t* sA = sm;                       // 8448
    uint32_t* sB = sm + 64 * ABLK;           // 25344
    uint32_t* stage = sB + 384 * BBLK;       // 16384
    float* sbias = (float*)(stage + 16384);  // 384

    int tid = threadIdx.x, w = tid >> 5, lane = tid & 31;
    int wm = w >> 2, wn = w & 3, g = lane >> 2, t = lane & 3;
    uint32_t stage_a = (uint32_t)__cvta_generic_to_shared(stage);
    uint64_t pol = mkpol_ef();

    for (int i = tid; i < 384 * 32; i += 1024) {
        int blk = i >> 5, l = i & 31;
        *(uint2*)(sB + blk * BBLK + l * 2) = *(const uint2*)(g_WhQKV + blk * 64 + l * 2);
    }
    if (tid < 128) {
        sbias[tid] = bq[tid];
        sbias[128 + tid] = bk[tid];
        sbias[256 + tid] = bv[tid];
    }

    int r0 = tid >> 5, c0 = (tid & 31) * 4;
    const int M = NN;
    int nT = (M + 127) >> 7;
    int tt = blockIdx.x;
    if (tt < nT) {
        int base = tt << 7;
#pragma unroll
        for (int ii = 0; ii < 4; ii++) {
            int r = r0 + ii * 32;
            int rowc = min(base + r, M - 1);
            cpasync16_ef(stage_a + (uint32_t)(r * 128 + c0) * 4, X + (size_t)rowc * 128 + c0, pol);
        }
        CP_COMMIT();
    }

    for (; tt < nT; tt += gridDim.x) {
        int base = tt << 7;
        CP_WAIT0();
        __syncthreads();
#pragma unroll
        for (int ii = 0; ii < 4; ii++) {
            int r = r0 + ii * 32;
            uint4 raw = *(const uint4*)(stage + r * 128 + c0);
            int w0 = aidx16(r, c0);
            sA[w0] = pk2(__uint_as_float(raw.x), __uint_as_float(raw.y));
            sA[w0 + 4] = pk2(__uint_as_float(raw.z), __uint_as_float(raw.w));
        }
        __syncthreads();
        int tn = tt + gridDim.x;
        if (tn < nT) {
            int nb = tn << 7;
#pragma unroll
            for (int ii = 0; ii < 4; ii++) {
                int r = r0 + ii * 32;
                int rowc = min(nb + r, M - 1);
                cpasync16_ef(stage_a + (uint32_t)(r * 128 + c0) * 4, X + (size_t)rowc * 128 + c0,
                             pol);
            }
            CP_COMMIT();
        }

        int row = base + wm * 16 + g;
#pragma unroll
        for (int sel = 0; sel < 3; sel++) {
            uint32_t* Y = sel == 0 ? Yq : sel == 1 ? Yk : Yv;
            float c_[4][4];
#pragma unroll
            for (int nt = 0; nt < 4; nt++)
#pragma unroll
                for (int i = 0; i < 4; i++) c_[nt][i] = 0.f;
#pragma unroll
            for (int ks = 0; ks < 8; ks++) {
                uint32_t a[4];
                *(uint4*)a = *(const uint4*)(sA + ABLK * (wm * 8 + ks) + lane * 4);
#pragma unroll
                for (int nt = 0; nt < 4; nt++) {
                    uint32_t b[2];
                    int blk = (sel * 16 + wn * 4 + nt) * 8 + ks;
                    *(uint2*)b = *(const uint2*)(sB + BBLK * blk + lane * 2);
                    mma16(c_[nt], a, b);
                }
            }
#pragma unroll
            for (int nt = 0; nt < 4; nt++) {
                int col = wn * 32 + nt * 8 + t * 2;
                float b0 = sbias[sel * 128 + col], b1 = sbias[sel * 128 + col + 1];
                if (row < M)
                    Y[(size_t)row * 64 + (col >> 1)] = pk2(c_[nt][0] + b0, c_[nt][1] + b1);
                if (row + 8 < M)
                    Y[(size_t)(row + 8) * 64 + (col >> 1)] = pk2(c_[nt][2] + b0, c_[nt][3] + b1);
            }
        }
    }
}

// ----------------------------- fused edge pass ------------------------------
// [e|m](perm) = EF @ WhEM2 ; p = exp((m+bm)*(q[src]-k[dst]) + e+be)
// den[dst] += p ; h[dst] += p*v[src]. Streams EF -> outE. B via ldmatrix.x4.
__global__ __launch_bounds__(1024, 1) void edge_tc(
    const float* __restrict__ EF, const float* __restrict__ be,
    const float* __restrict__ bm, const int* __restrict__ src,
    const int* __restrict__ dst, float* __restrict__ outE) {
    extern __shared__ __align__(16) uint32_t sm[];
    uint32_t* sA = sm;                       // 8448
    uint32_t* sB = sm + 8448;                // 16384 (LDSM row order, no pad)
    uint32_t* stage = sB + 16384;            // 16384
    float* sbe = (float*)(stage + 16384);
    float* sbm = sbe + 128;

    int tid = threadIdx.x, w = tid >> 5, lane = tid & 31;
    int wm = w >> 2, wn = w & 3, g = lane >> 2, t = lane & 3;
    int chb = wn * 32 + t * 8;
    int chw = chb >> 1;  // half2 word offset within row
    uint32_t stage_a = (uint32_t)__cvta_generic_to_shared(stage);
    uint32_t sB_a = (uint32_t)__cvta_generic_to_shared(sB);
    uint64_t pol = mkpol_ef();

    for (int i = tid * 4; i < 16384; i += 1024 * 4)
        *(uint4*)(sB + i) = *(const uint4*)(g_WhEM2 + i);
    if (tid < 128) {
        sbe[tid] = be[tid];
        sbm[tid] = bm[tid];
    }

    int r0 = tid >> 5, c0 = (tid & 31) * 4;
    int rl0 = wm * 16 + g, rl1 = rl0 + 8;

    const int nT = NE / 128;  // 6250 exact
    int tt = blockIdx.x;
    if (tt < nT) {
        int base = tt << 7;
#pragma unroll
        for (int ii = 0; ii < 4; ii++) {
            int r = r0 + ii * 32;
            cpasync16_ef(stage_a + (uint32_t)(r * 128 + c0) * 4,
                         EF + (size_t)(base + r) * 128 + c0, pol);
        }
        CP_COMMIT();
    }

    for (; tt < nT; tt += gridDim.x) {
        int base = tt << 7;
        int s0 = __ldg(src + base + rl0), d0 = __ldg(dst + base + rl0);
        int s1 = __ldg(src + base + rl1), d1 = __ldg(dst + base + rl1);
        CP_WAIT0();
        __syncthreads();
#pragma unroll
        for (int ii = 0; ii < 4; ii++) {
            int r = r0 + ii * 32;
            uint4 raw = *(const uint4*)(stage + r * 128 + c0);
            float4 x;
            x.x = __uint_as_float(raw.x); x.y = __uint_as_float(raw.y);
            x.z = __uint_as_float(raw.z); x.w = __uint_as_float(raw.w);
            __stcs((float4*)(outE + (size_t)(base + r) * 128 + c0), x);  // passthrough
            int w0 = aidx16(r, c0);
            sA[w0] = pk2(x.x, x.y);
            sA[w0 + 4] = pk2(x.z, x.w);
        }
        __syncthreads();
        int tn = tt + gridDim.x;
        if (tn < nT) {
            int nb = tn << 7;
#pragma unroll
            for (int ii = 0; ii < 4; ii++) {
                int r = r0 + ii * 32;
                cpasync16_ef(stage_a + (uint32_t)(r * 128 + c0) * 4,
                             EF + (size_t)(nb + r) * 128 + c0, pol);
            }
            CP_COMMIT();
        }

        float c_[8][4];
#pragma unroll
        for (int nt = 0; nt < 8; nt++)
#pragma unroll
            for (int i = 0; i < 4; i++) c_[nt][i] = 0.f;
#pragma unroll
        for (int ks = 0; ks < 8; ks++) {
            uint32_t a[4];
            *(uint4*)a = *(const uint4*)(sA + ABLK * (wm * 8 + ks) + lane * 4);
#pragma unroll
            for (int ntp = 0; ntp < 4; ntp++) {
                uint32_t r[4];
                ldsm4(r, sB_a + (uint32_t)((((wn * 4 + ntp) * 8 + ks) * 128 + lane * 4) * 4));
                mma16(c_[2 * ntp], a, r);
                mma16(c_[2 * ntp + 1], a, r + 2);
            }
        }

        // epilogue: hoisted gathers (MLP=6), then exp + red
        uint4 qw0 = __ldg((const uint4*)(g_qh + (size_t)s0 * 64 + chw));
        uint4 kw0 = __ldg((const uint4*)(g_kh + (size_t)d0 * 64 + chw));
        uint4 vw0 = __ldg((const uint4*)(g_vh + (size_t)s0 * 64 + chw));
        uint4 qw1 = __ldg((const uint4*)(g_qh + (size_t)s1 * 64 + chw));
        uint4 kw1 = __ldg((const uint4*)(g_kh + (size_t)d1 * 64 + chw));
        uint4 vw1 = __ldg((const uint4*)(g_vh + (size_t)s1 * 64 + chw));
#pragma unroll
        for (int rs = 0; rs < 2; rs++) {
            int d = rs ? d1 : d0;
            uint4 qw = rs ? qw1 : qw0;
            uint4 kw = rs ? kw1 : kw0;
            uint4 vw = rs ? vw1 : vw0;
            float qa[8], ka[8], va[8];
            {
                const uint32_t* qq = (const uint32_t*)&qw;
                const uint32_t* kk = (const uint32_t*)&kw;
                const uint32_t* vv = (const uint32_t*)&vw;
#pragma unroll
                for (int ww = 0; ww < 4; ww++) {
                    float2 f;
                    f = __half22float2(*(const __half2*)&qq[ww]);
                    qa[ww * 2] = f.x; qa[ww * 2 + 1] = f.y;
                    f = __half22float2(*(const __half2*)&kk[ww]);
                    ka[ww * 2] = f.x; ka[ww * 2 + 1] = f.y;
                    f = __half22float2(*(const __half2*)&vv[ww]);
                    va[ww * 2] = f.x; va[ww * 2 + 1] = f.y;
                }
            }
            float p[8], pv[8];
#pragma unroll
            for (int nt = 0; nt < 8; nt++) {
                float ev = c_[nt][rs * 2] + sbe[chb + nt];
                float mv = c_[nt][rs * 2 + 1] + sbm[chb + nt];
                p[nt] = __expf(fmaf(mv, qa[nt] - ka[nt], ev));
                pv[nt] = p[nt] * va[nt];
            }
            float4* dp = (float4*)(g_den + (size_t)d * 128 + chb);
            float4* hp = (float4*)(g_h + (size_t)d * 128 + chb);
            atomicAdd(dp, make_float4(p[0], p[1], p[2], p[3]));
            atomicAdd(dp + 1, make_float4(p[4], p[5], p[6], p[7]));
            atomicAdd(hp, make_float4(pv[0], pv[1], pv[2], pv[3]));
            atomicAdd(hp + 1, make_float4(pv[4], pv[5], pv[6], pv[7]));
        }
    }
}

// ----------------------------- final fused MLP (tf32, unchanged) -----------
__global__ __launch_bounds__(256, 1) void final_tc(
    const float* __restrict__ NF, const float* __restrict__ bf1,
    const float* __restrict__ gln, const float* __restrict__ bln,
    float* __restrict__ out) {
    extern __shared__ __align__(16) uint32_t sm[];
    uint32_t* sA = sm;
    uint32_t* sB1 = sm + 128 * PIT;
    uint32_t* sB2 = sm + 2 * 128 * PIT;
    float* smu = (float*)(sm + 3 * 128 * PIT);
    float* sinv = smu + 128;
    float* sgl = sinv + 128;
    float* sbl = sgl + 128;

    int tid = threadIdx.x, w = tid >> 5, lane = tid & 31;
    int wm = w >> 2, wn = w & 3, g = lane >> 2, t = lane & 3;

    for (int i = tid; i < 128 * 32; i += 256) {
        int r = i >> 5, c = (i & 31) * 4;
        *(uint4*)(sB1 + r * PIT + c) = *(const uint4*)(g_WtF1 + r * 128 + c);
        *(uint4*)(sB2 + r * PIT + c) = *(const uint4*)(g_WtF2g + r * 128 + c);
    }
    if (tid < 128) {
        sgl[tid] = gln[tid];
        sbl[tid] = bln[tid];
    }
    float b1c[4][2], vbc[4][2], vgc[4][2];
#pragma unroll
    for (int nt = 0; nt < 4; nt++) {
        int col = wn * 32 + nt * 8 + t * 2;
        b1c[nt][0] = __ldg(bf1 + col);   b1c[nt][1] = __ldg(bf1 + col + 1);
        vbc[nt][0] = g_vb[col];          vbc[nt][1] = g_vb[col + 1];
        vgc[nt][0] = g_vg[col];          vgc[nt][1] = g_vg[col + 1];
    }

    int srow = tid >> 1, shalf = tid & 1;
    const int nT = (NN + 127) >> 7;
    for (int tt = blockIdx.x; tt < nT; tt += gridDim.x) {
        __syncthreads();
        int base = tt << 7;
        for (int i = tid; i < 128 * 32; i += 256) {
            int r = i >> 5, c = (i & 31) * 4;
            int row = base + r;
            uint4 u = make_uint4(0u, 0u, 0u, 0u);
            if (row < NN) {
                float4 hh = *(const float4*)(g_h + (size_t)row * 128 + c);
                float4 dn = *(const float4*)(g_den + (size_t)row * 128 + c);
                float4 nf = *(const float4*)(NF + (size_t)row * 128 + c);
                u.x = rna((dn.x > 0.f ? hh.x / dn.x : 0.f) + nf.x);
                u.y = rna((dn.y > 0.f ? hh.y / dn.y : 0.f) + nf.y);
                u.z = rna((dn.z > 0.f ? hh.z / dn.z : 0.f) + nf.z);
                u.w = rna((dn.w > 0.f ? hh.w / dn.w : 0.f) + nf.w);
            }
            *(uint4*)(sA + r * PIT + c) = u;
        }
        __syncthreads();

        float c_[4][4][4];
#pragma unroll
        for (int mt = 0; mt < 4; mt++)
#pragma unroll
            for (int nt = 0; nt < 4; nt++)
#pragma unroll
                for (int i = 0; i < 4; i++) c_[mt][nt][i] = 0.f;
#pragma unroll
        for (int k0 = 0; k0 < 128; k0 += 8) {
            uint32_t a[4][4], b[4][2];
#pragma unroll
            for (int mt = 0; mt < 4; mt++) {
                int r = wm * 64 + mt * 16 + g;
                a[mt][0] = sA[r * PIT + k0 + t];
                a[mt][1] = sA[(r + 8) * PIT + k0 + t];
                a[mt][2] = sA[r * PIT + k0 + t + 4];
                a[mt][3] = sA[(r + 8) * PIT + k0 + t + 4];
            }
#pragma unroll
            for (int nt = 0; nt < 4; nt++) {
                int n = wn * 32 + nt * 8 + g;
                b[nt][0] = sB1[n * PIT + k0 + t];
                b[nt][1] = sB1[n * PIT + k0 + t + 4];
            }
#pragma unroll
            for (int mt = 0; mt < 4; mt++)
#pragma unroll
                for (int nt = 0; nt < 4; nt++) mma8(c_[mt][nt], a[mt], b[nt]);
        }
        __syncthreads();

#pragma unroll
        for (int mt = 0; mt < 4; mt++) {
            int r0 = wm * 64 + mt * 16 + g;
#pragma unroll
            for (int nt = 0; nt < 4; nt++) {
                int col = wn * 32 + nt * 8 + t * 2;
                uint2 u0, u1;
                u0.x = rna(mishf(c_[mt][nt][0] + b1c[nt][0]));
                u0.y = rna(mishf(c_[mt][nt][1] + b1c[nt][1]));
                u1.x = rna(mishf(c_[mt][nt][2] + b1c[nt][0]));
                u1.y = rna(mishf(c_[mt][nt][3] + b1c[nt][1]));
                *(uint2*)(sA + r0 * PIT + col) = u0;
                *(uint2*)(sA + (r0 + 8) * PIT + col) = u1;
            }
        }
        __syncthreads();

        {
            float s1 = 0.f, s2 = 0.f;
            const uint32_t* rp = sA + srow * PIT + shalf * 64;
#pragma unroll
            for (int i = 0; i < 16; i++) {
                uint4 uu = *(const uint4*)(rp + i * 4);
                float x0 = __uint_as_float(uu.x), x1 = __uint_as_float(uu.y);
                float x2 = __uint_as_float(uu.z), x3 = __uint_as_float(uu.w);
                s1 += x0 + x1 + x2 + x3;
                s2 += x0 * x0 + x1 * x1 + x2 * x2 + x3 * x3;
            }
            s1 += __shfl_xor_sync(0xffffffffu, s1, 1);
            s2 += __shfl_xor_sync(0xffffffffu, s2, 1);
            if (shalf == 0) {
                float mu = s1 * (1.f / 128.f);
                smu[srow] = mu;
                sinv[srow] = rsqrtf(s2 * (1.f / 128.f) - mu * mu + 1e-5f);
            }
        }
        __syncthreads();

        float c2[4][4][4];
#pragma unroll
        for (int mt = 0; mt < 4; mt++)
#pragma unroll
            for (int nt = 0; nt < 4; nt++)
#pragma unroll
                for (int i = 0; i < 4; i++) c2[mt][nt][i] = 0.f;
#pragma unroll
        for (int k0 = 0; k0 < 128; k0 += 8) {
            uint32_t a[4][4], b[4][2];
#pragma unroll
            for (int mt = 0; mt < 4; mt++) {
                int r = wm * 64 + mt * 16 + g;
                a[mt][0] = sA[r * PIT + k0 + t];
                a[mt][1] = sA[(r + 8) * PIT + k0 + t];
                a[mt][2] = sA[r * PIT + k0 + t + 4];
                a[mt][3] = sA[(r + 8) * PIT + k0 + t + 4];
            }
#pragma unroll
            for (int nt = 0; nt < 4; nt++) {
                int n = wn * 32 + nt * 8 + g;
                b[nt][0] = sB2[n * PIT + k0 + t];
                b[nt][1] = sB2[n * PIT + k0 + t + 4];
            }
#pragma unroll
            for (int mt = 0; mt < 4; mt++)
#pragma unroll
                for (int nt = 0; nt < 4; nt++) mma8(c2[mt][nt], a[mt], b[nt]);
        }
        __syncthreads();

#pragma unroll
        for (int mt = 0; mt < 4; mt++) {
            int r0 = wm * 64 + mt * 16 + g;
            float mu0 = smu[r0], iv0 = sinv[r0];
            float mu8 = smu[r0 + 8], iv8 = sinv[r0 + 8];
#pragma unroll
            for (int nt = 0; nt < 4; nt++) {
                int col = wn * 32 + nt * 8 + t * 2;
                uint2 y0, y1;
                y0.x = __float_as_uint(iv0 * c2[mt][nt][0] + vbc[nt][0] - mu0 * iv0 * vgc[nt][0]);
                y0.y = __float_as_uint(iv0 * c2[mt][nt][1] + vbc[nt][1] - mu0 * iv0 * vgc[nt][1]);
                y1.x = __float_as_uint(iv8 * c2[mt][nt][2] + vbc[nt][0] - mu8 * iv8 * vgc[nt][0]);
                y1.y = __float_as_uint(iv8 * c2[mt][nt][3] + vbc[nt][1] - mu8 * iv8 * vgc[nt][1]);
                *(uint2*)(sA + r0 * PIT + col) = y0;
                *(uint2*)(sA + (r0 + 8) * PIT + col) = y1;
            }
        }
        __syncthreads();

        {
            float s1 = 0.f, s2 = 0.f;
            const uint32_t* rp = sA + srow * PIT + shalf * 64;
#pragma unroll
            for (int i = 0; i < 16; i++) {
                uint4 uu = *(const uint4*)(rp + i * 4);
                float x0 = __uint_as_float(uu.x), x1 = __uint_as_float(uu.y);
                float x2 = __uint_as_float(uu.z), x3 = __uint_as_float(uu.w);
                s1 += x0 + x1 + x2 + x3;
                s2 += x0 * x0 + x1 * x1 + x2 * x2 + x3 * x3;
            }
            s1 += __shfl_xor_sync(0xffffffffu, s1, 1);
            s2 += __shfl_xor_sync(0xffffffffu, s2, 1);
            if (shalf == 0) {
                float mu = s1 * (1.f / 128.f);
                smu[srow] = mu;
                sinv[srow] = rsqrtf(s2 * (1.f / 128.f) - mu * mu + 1e-5f);
            }
        }
        __syncthreads();

        {
            int row = base + srow;
            if (row < NN) {
                float mu = smu[srow], iv = sinv[srow];
                const uint32_t* rp = sA + srow * PIT + shalf * 64;
#pragma unroll
                for (int i = 0; i < 16; i++) {
                    int col = shalf * 64 + i * 4;
                    uint4 uu = *(const uint4*)(rp + i * 4);
                    float4 o;
                    o.x = (__uint_as_float(uu.x) - mu) * iv * sgl[col + 0] + sbl[col + 0];
                    o.y = (__uint_as_float(uu.y) - mu) * iv * sgl[col + 1] + sbl[col + 1];
                    o.z = (__uint_as_float(uu.z) - mu) * iv * sgl[col + 2] + sbl[col + 2];
                    o.w = (__uint_as_float(uu.w) - mu) * iv * sgl[col + 3] + sbl[col + 3];
                    *(float4*)(out + (size_t)row * 128 + col) = o;
                }
            }
        }
    }
}

// ---------------------------------------------------------------------------
extern "C" void kernel_launch(void* const* d_in, const int* in_sizes, int n_in,
                              void* d_out, int out_size) {
    const float* node_feats = (const float*)d_in[0];
    const float* edge_feats = (const float*)d_in[1];
    const int* src = (const int*)d_in[2];
    const int* dst = (const int*)d_in[3];
    const float* Wq = (const float*)d_in[4];
    const float* bq = (const float*)d_in[5];
    const float* Wk = (const float*)d_in[6];
    const float* bk = (const float*)d_in[7];
    const float* Wv = (const float*)d_in[8];
    const float* bv = (const float*)d_in[9];
    const float* We = (const float*)d_in[10];
    const float* be = (const float*)d_in[11];
    const float* Wm = (const float*)d_in[12];
    const float* bm = (const float*)d_in[13];
    const float* Wf1 = (const float*)d_in[14];
    const float* bf1 = (const float*)d_in[15];
    const float* g_f = (const float*)d_in[16];
    const float* b_f = (const float*)d_in[17];
    const float* Wf2 = (const float*)d_in[18];
    const float* bf2 = (const float*)d_in[19];
    const float* g_ln = (const float*)d_in[20];
    const float* b_ln = (const float*)d_in[21];
    float* out = (float*)d_out;

    void *pden, *ph, *pq, *pk, *pv;
    cudaGetSymbolAddress(&pden, g_den);
    cudaGetSymbolAddress(&ph, g_h);
    cudaGetSymbolAddress(&pq, g_qh);
    cudaGetSymbolAddress(&pk, g_kh);
    cudaGetSymbolAddress(&pv, g_vh);

    const size_t QKV_SMEM = (size_t)(64 * ABLK + 384 * BBLK + 16384 + 384) * 4;  // 202240
    const size_t EDGE_SMEM = (size_t)(8448 + 16384 + 16384 + 256) * 4;           // 165888
    const size_t FIN_SMEM = (size_t)(3 * 128 * PIT + 512) * 4;                   // 204800
    cudaFuncSetAttribute(qkv_tc, cudaFuncAttributeMaxDynamicSharedMemorySize, (int)QKV_SMEM);
    cudaFuncSetAttribute(edge_tc, cudaFuncAttributeMaxDynamicSharedMemorySize, (int)EDGE_SMEM);
    cudaFuncSetAttribute(final_tc, cudaFuncAttributeMaxDynamicSharedMemorySize, (int)FIN_SMEM);

    cudaMemsetAsync(pden, 0, (size_t)NN * 128 * sizeof(float), 0);
    cudaMemsetAsync(ph, 0, (size_t)NN * 128 * sizeof(float), 0);

    prep_T<<<64, 128>>>(Wq, Wk, Wv, We, Wm, Wf1, Wf2, g_f);
    prep_V<<<1, 128>>>(Wf2, b_f, g_f, bf2);

    qkv_tc<<<148, 1024, QKV_SMEM>>>(node_feats, bq, bk, bv, (uint32_t*)pq, (uint32_t*)pk,
                                    (uint32_t*)pv);

    edge_tc<<<148, 1024, EDGE_SMEM>>>(edge_feats, be, bm, src, dst, out + (size_t)NN * 128);

    final_tc<<<148, 256, FIN_SMEM>>>(node_feats, bf1, g_ln, b_ln, out);
}

// round 12
// speedup vs baseline: 1.1090x; 1.1090x over previous
#include <cuda_runtime.h>
#include <cuda_fp16.h>
#include <cstdint>
#include <math.h>

#define NN 50000
#define NE 800000

// fp16 fragment-major strides (32-bit words)
#define ABLK 132  // A block (16r x 16k): 32 lanes x 4 words, pad 128->132
#define BBLK 66   // B block (8n x 16k): 32 lanes x 2 words, pad 64->66
#define PIT 132   // legacy tf32 pitch for final_tc

// ----------------------------- scratch globals -----------------------------
__device__ uint32_t g_qh[NN * 64];  // q rows, fp16 half2 words
__device__ uint32_t g_kh[NN * 64];
__device__ uint32_t g_vh[NN * 64];
__device__ float g_den[NN * 128];
__device__ float g_h[NN * 128];

__device__ uint32_t g_WhQKV[384 * 128];  // packed [Wq|Wk|Wv], fp16 frag-major
__device__ uint32_t g_WhEM[256 * 128];   // channel-permuted [We|Wm], fp16 frag-major
__device__ uint32_t g_WtF1[128 * 128];   // tf32 [n][k] for final_tc
__device__ uint32_t g_WtF2g[128 * 128];
__device__ float g_vb[128];
__device__ float g_vg[128];

// ----------------------------- helpers -------------------------------------
__device__ __forceinline__ uint32_t rna(float x) {
    uint32_t r;
    asm("cvt.rna.tf32.f32 %0, %1;" : "=r"(r) : "f"(x));
    return r;
}
__device__ __forceinline__ uint32_t pk2(float a, float b) {
    __half2 h = __floats2half2_rn(a, b);
    return *reinterpret_cast<uint32_t*>(&h);
}
__device__ __forceinline__ void mma16(float* c, const uint32_t* a, const uint32_t* b) {
    asm volatile(
        "mma.sync.aligned.m16n8k16.row.col.f32.f16.f16.f32 "
        "{%0,%1,%2,%3}, {%4,%5,%6,%7}, {%8,%9}, {%0,%1,%2,%3};"
        : "+f"(c[0]), "+f"(c[1]), "+f"(c[2]), "+f"(c[3])
        : "r"(a[0]), "r"(a[1]), "r"(a[2]), "r"(a[3]), "r"(b[0]), "r"(b[1]));
}
__device__ __forceinline__ void mma8(float* c, const uint32_t* a, const uint32_t* b) {
    asm volatile(
        "mma.sync.aligned.m16n8k8.row.col.f32.tf32.tf32.f32 "
        "{%0,%1,%2,%3}, {%4,%5,%6,%7}, {%8,%9}, {%0,%1,%2,%3};"
        : "+f"(c[0]), "+f"(c[1]), "+f"(c[2]), "+f"(c[3])
        : "r"(a[0]), "r"(a[1]), "r"(a[2]), "r"(a[3]), "r"(b[0]), "r"(b[1]));
}
__device__ __forceinline__ float mishf(float x) {
    float sp = (x > 20.f) ? x : log1pf(__expf(x));
    return x * tanhf(sp);
}
__device__ __forceinline__ uint64_t mkpol_ef() {
    uint64_t p;
    asm("createpolicy.fractional.L2::evict_first.b64 %0, 1.0;" : "=l"(p));
    return p;
}
__device__ __forceinline__ void cpasync16_ef(uint32_t saddr, const void* g, uint64_t pol) {
    asm volatile("cp.async.cg.shared.global.L2::cache_hint [%0], [%1], 16, %2;"
                 ::"r"(saddr), "l"(g), "l"(pol));
}
#define CP_COMMIT() asm volatile("cp.async.commit_group;" ::: "memory")
#define CP_WAIT0() asm volatile("cp.async.wait_group 0;" ::: "memory")

// fp16 frag-major gmem word index for B value pair (n, k2), k2 = k>>1
__device__ __forceinline__ int fidx16(int n, int k2) {
    return (((n >> 3) << 3) + (k2 >> 3)) * 64 + (((((n & 7) << 2) | (k2 & 3))) << 1) +
           ((k2 >> 2) & 1);
}
// fp16 frag-major smem word index for A halves (r, c), c multiple of 4
__device__ __forceinline__ int aidx16(int r, int c) {
    return ABLK * (((r >> 4) << 3) + (c >> 4)) + ((((r & 7) << 2) | ((c >> 1) & 3)) << 2) +
           ((r >> 3) & 1) + (((c >> 3) & 1) << 1);
}

// ----------------------------- prep kernels --------------------------------
__global__ void prep_T(const float* __restrict__ Wq, const float* __restrict__ Wk,
                       const float* __restrict__ Wv, const float* __restrict__ We,
                       const float* __restrict__ Wm, const float* __restrict__ Wf1,
                       const float* __restrict__ Wf2, const float* __restrict__ gf) {
    int k2 = blockIdx.x, n = threadIdx.x;
    int k0 = k2 * 2, k1 = k0 + 1;
    g_WhQKV[fidx16(n, k2)] = pk2(Wq[k0 * 128 + n], Wq[k1 * 128 + n]);
    g_WhQKV[fidx16(128 + n, k2)] = pk2(Wk[k0 * 128 + n], Wk[k1 * 128 + n]);
    g_WhQKV[fidx16(256 + n, k2)] = pk2(Wv[k0 * 128 + n], Wv[k1 * 128 + n]);
    g_WtF1[n * 128 + k0] = rna(Wf1[k0 * 128 + n]);
    g_WtF1[n * 128 + k1] = rna(Wf1[k1 * 128 + n]);
    g_WtF2g[n * 128 + k0] = rna(gf[k0] * Wf2[k0 * 128 + n]);
    g_WtF2g[n * 128 + k1] = rna(gf[k1] * Wf2[k1 * 128 + n]);
    // EM permutation: GEMM col j -> channel. Thread (wn,t) owns quads
    // cA = wn*32 + t*4 (nt 0..3) and cB = cA+16 (nt 4..7) -> coalesced REDs.
#pragma unroll
    for (int jj = 0; jj < 2; jj++) {
        int j = n + jj * 128;
        int wn = j >> 6, wi = j & 63, nt = wi >> 3, rem = wi & 7, tt = rem >> 1, par = rem & 1;
        int ch = wn * 32 + ((nt >> 2) << 4) + tt * 4 + (nt & 3);
        const float* W = par ? Wm : We;
        g_WhEM[fidx16(j, k2)] = pk2(W[k0 * 128 + ch], W[k1 * 128 + ch]);
    }
}

__global__ void prep_V(const float* __restrict__ Wf2, const float* __restrict__ bf,
                       const float* __restrict__ gf, const float* __restrict__ bf2) {
    int n = threadIdx.x;
    float a = 0.f, b = 0.f;
    for (int k = 0; k < 128; k++) {
        float w = Wf2[k * 128 + n];
        a = fmaf(bf[k], w, a);
        b = fmaf(gf[k], w, b);
    }
    g_vb[n] = bf2[n] + a;
    g_vg[n] = b;
}

// ----------------------------- fused QKV linear -----------------------------
// q/k/v = NF @ [Wq|Wk|Wv] + b, outputs stored fp16 (half2 words).
__global__ __launch_bounds__(1024, 1) void qkv_tc(
    const float* __restrict__ X,
    const float* __restrict__ bq, const float* __restrict__ bk,
    const float* __restrict__ bv,
    uint32_t* __restrict__ Yq, uint32_t* __restrict__ Yk, uint32_t* __restrict__ Yv) {
    extern __shared__ __align__(16) uint32_t sm[];
    uint32_t* sA = sm;                       // 8448
    uint32_t* sB = sm + 64 * ABLK;           // 25344
    uint32_t* stage = sB + 384 * BBLK;       // 16384
    float* sbias = (float*)(stage + 16384);  // 384

    int tid = threadIdx.x, w = tid >> 5, lane = tid & 31;
    int wm = w >> 2, wn = w & 3, g = lane >> 2, t = lane & 3;
    uint32_t stage_a = (uint32_t)__cvta_generic_to_shared(stage);
    uint64_t pol = mkpol_ef();

    for (int i = tid; i < 384 * 32; i += 1024) {
        int blk = i >> 5, l = i & 31;
        *(uint2*)(sB + blk * BBLK + l * 2) = *(const uint2*)(g_WhQKV + blk * 64 + l * 2);
    }
    if (tid < 128) {
        sbias[tid] = bq[tid];
        sbias[128 + tid] = bk[tid];
        sbias[256 + tid] = bv[tid];
    }

    int r0 = tid >> 5, c0 = (tid & 31) * 4;
    const int M = NN;
    int nT = (M + 127) >> 7;
    int tt = blockIdx.x;
    if (tt < nT) {
        int base = tt << 7;
#pragma unroll
        for (int ii = 0; ii < 4; ii++) {
            int r = r0 + ii * 32;
            int rowc = min(base + r, M - 1);
            cpasync16_ef(stage_a + (uint32_t)(r * 128 + c0) * 4, X + (size_t)rowc * 128 + c0, pol);
        }
        CP_COMMIT();
    }

    for (; tt < nT; tt += gridDim.x) {
        int base = tt << 7;
        CP_WAIT0();
        __syncthreads();
#pragma unroll
        for (int ii = 0; ii < 4; ii++) {
            int r = r0 + ii * 32;
            uint4 raw = *(const uint4*)(stage + r * 128 + c0);
            int w0 = aidx16(r, c0);
            sA[w0] = pk2(__uint_as_float(raw.x), __uint_as_float(raw.y));
            sA[w0 + 4] = pk2(__uint_as_float(raw.z), __uint_as_float(raw.w));
        }
        __syncthreads();
        int tn = tt + gridDim.x;
        if (tn < nT) {
            int nb = tn << 7;
#pragma unroll
            for (int ii = 0; ii < 4; ii++) {
                int r = r0 + ii * 32;
                int rowc = min(nb + r, M - 1);
                cpasync16_ef(stage_a + (uint32_t)(r * 128 + c0) * 4, X + (size_t)rowc * 128 + c0,
                             pol);
            }
            CP_COMMIT();
        }

        int row = base + wm * 16 + g;
#pragma unroll
        for (int sel = 0; sel < 3; sel++) {
            uint32_t* Y = sel == 0 ? Yq : sel == 1 ? Yk : Yv;
            float c_[4][4];
#pragma unroll
            for (int nt = 0; nt < 4; nt++)
#pragma unroll
                for (int i = 0; i < 4; i++) c_[nt][i] = 0.f;
#pragma unroll
            for (int ks = 0; ks < 8; ks++) {
                uint32_t a[4];
                *(uint4*)a = *(const uint4*)(sA + ABLK * (wm * 8 + ks) + lane * 4);
#pragma unroll
                for (int nt = 0; nt < 4; nt++) {
                    uint32_t b[2];
                    int blk = (sel * 16 + wn * 4 + nt) * 8 + ks;
                    *(uint2*)b = *(const uint2*)(sB + BBLK * blk + lane * 2);
                    mma16(c_[nt], a, b);
                }
            }
#pragma unroll
            for (int nt = 0; nt < 4; nt++) {
                int col = wn * 32 + nt * 8 + t * 2;
                float b0 = sbias[sel * 128 + col], b1 = sbias[sel * 128 + col + 1];
                if (row < M)
                    Y[(size_t)row * 64 + (col >> 1)] = pk2(c_[nt][0] + b0, c_[nt][1] + b1);
                if (row + 8 < M)
                    Y[(size_t)(row + 8) * 64 + (col >> 1)] = pk2(c_[nt][2] + b0, c_[nt][3] + b1);
            }
        }
    }
}

// ----------------------------- fused edge pass ------------------------------
// [e|m](perm) = EF @ WhEM ; p = exp((m+bm)*(q[src]-k[dst]) + e+be)
// den[dst] += p ; h[dst] += p*v[src]. Streams EF -> outE. R9 tile flow;
// channel mapping gives coalesced RED footprints (64B/row per red.v4).
__global__ __launch_bounds__(1024, 1) void edge_tc(
    const float* __restrict__ EF, const float* __restrict__ be,
    const float* __restrict__ bm, const int* __restrict__ src,
    const int* __restrict__ dst, float* __restrict__ outE) {
    extern __shared__ __align__(16) uint32_t sm[];
    uint32_t* sA = sm;                       // 8448
    uint32_t* sB = sm + 64 * ABLK;           // 16896
    uint32_t* stage = sB + 256 * BBLK;       // 16384
    float* sbe = (float*)(stage + 16384);
    float* sbm = sbe + 128;

    int tid = threadIdx.x, w = tid >> 5, lane = tid & 31;
    int wm = w >> 2, wn = w & 3, g = lane >> 2, t = lane & 3;
    int cA = wn * 32 + t * 4;   // quad A channels
    int cB = cA + 16;           // quad B channels
    int cAw = cA >> 1, cBw = cB >> 1;  // half2 word offsets
    uint32_t stage_a = (uint32_t)__cvta_generic_to_shared(stage);
    uint64_t pol = mkpol_ef();

    for (int i = tid; i < 256 * 32; i += 1024) {
        int blk = i >> 5, l = i & 31;
        *(uint2*)(sB + blk * BBLK + l * 2) = *(const uint2*)(g_WhEM + blk * 64 + l * 2);
    }
    if (tid < 128) {
        sbe[tid] = be[tid];
        sbm[tid] = bm[tid];
    }

    int r0 = tid >> 5, c0 = (tid & 31) * 4;
    int rl0 = wm * 16 + g, rl1 = rl0 + 8;

    const int nT = NE / 128;  // 6250 exact
    int tt = blockIdx.x;
    if (tt < nT) {
        int base = tt << 7;
#pragma unroll
        for (int ii = 0; ii < 4; ii++) {
            int r = r0 + ii * 32;
            cpasync16_ef(stage_a + (uint32_t)(r * 128 + c0) * 4,
                         EF + (size_t)(base + r) * 128 + c0, pol);
        }
        CP_COMMIT();
    }

    for (; tt < nT; tt += gridDim.x) {
        int base = tt << 7;
        int s0 = __ldg(src + base + rl0), d0 = __ldg(dst + base + rl0);
        int s1 = __ldg(src + base + rl1), d1 = __ldg(dst + base + rl1);
        CP_WAIT0();
        __syncthreads();
#pragma unroll
        for (int ii = 0; ii < 4; ii++) {
            int r = r0 + ii * 32;
            uint4 raw = *(const uint4*)(stage + r * 128 + c0);
            float4 x;
            x.x = __uint_as_float(raw.x); x.y = __uint_as_float(raw.y);
            x.z = __uint_as_float(raw.z); x.w = __uint_as_float(raw.w);
            __stcs((float4*)(outE + (size_t)(base + r) * 128 + c0), x);  // passthrough
            int w0 = aidx16(r, c0);
            sA[w0] = pk2(x.x, x.y);
            sA[w0 + 4] = pk2(x.z, x.w);
        }
        __syncthreads();
        int tn = tt + gridDim.x;
        if (tn < nT) {
            int nb = tn << 7;
#pragma unroll
            for (int ii = 0; ii < 4; ii++) {
                int r = r0 + ii * 32;
                cpasync16_ef(stage_a + (uint32_t)(r * 128 + c0) * 4,
                             EF + (size_t)(nb + r) * 128 + c0, pol);
            }
            CP_COMMIT();
        }

        float c_[8][4];
#pragma unroll
        for (int nt = 0; nt < 8; nt++)
#pragma unroll
            for (int i = 0; i < 4; i++) c_[nt][i] = 0.f;
#pragma unroll
        for (int ks = 0; ks < 8; ks++) {
            uint32_t a[4];
            *(uint4*)a = *(const uint4*)(sA + ABLK * (wm * 8 + ks) + lane * 4);
#pragma unroll
            for (int nt = 0; nt < 8; nt++) {
                uint32_t b[2];
                *(uint2*)b = *(const uint2*)(sB + BBLK * ((wn * 8 + nt) * 8 + ks) + lane * 2);
                mma16(c_[nt], a, b);
            }
        }

        // epilogue: thread owns channels cA..cA+3 (nt 0..3) and cB..cB+3 (nt 4..7)
#pragma unroll
        for (int rs = 0; rs < 2; rs++) {
            int s = rs ? s1 : s0, d = rs ? d1 : d0;
            uint2 qA = __ldg((const uint2*)(g_qh + (size_t)s * 64 + cAw));
            uint2 qB = __ldg((const uint2*)(g_qh + (size_t)s * 64 + cBw));
            uint2 kA = __ldg((const uint2*)(g_kh + (size_t)d * 64 + cAw));
            uint2 kB = __ldg((const uint2*)(g_kh + (size_t)d * 64 + cBw));
            uint2 vA = __ldg((const uint2*)(g_vh + (size_t)s * 64 + cAw));
            uint2 vB = __ldg((const uint2*)(g_vh + (size_t)s * 64 + cBw));
            float qa[8], ka[8], va[8];
            {
                float2 f;
                f = __half22float2(*(const __half2*)&qA.x); qa[0] = f.x; qa[1] = f.y;
                f = __half22float2(*(const __half2*)&qA.y); qa[2] = f.x; qa[3] = f.y;
                f = __half22float2(*(const __half2*)&qB.x); qa[4] = f.x; qa[5] = f.y;
                f = __half22float2(*(const __half2*)&qB.y); qa[6] = f.x; qa[7] = f.y;
                f = __half22float2(*(const __half2*)&kA.x); ka[0] = f.x; ka[1] = f.y;
                f = __half22float2(*(const __half2*)&kA.y); ka[2] = f.x; ka[3] = f.y;
                f = __half22float2(*(const __half2*)&kB.x); ka[4] = f.x; ka[5] = f.y;
                f = __half22float2(*(const __half2*)&kB.y); ka[6] = f.x; ka[7] = f.y;
                f = __half22float2(*(const __half2*)&vA.x); va[0] = f.x; va[1] = f.y;
                f = __half22float2(*(const __half2*)&vA.y); va[2] = f.x; va[3] = f.y;
                f = __half22float2(*(const __half2*)&vB.x); va[4] = f.x; va[5] = f.y;
                f = __half22float2(*(const __half2*)&vB.y); va[6] = f.x; va[7] = f.y;
            }
            float p[8], pv[8];
#pragma unroll
            for (int nt = 0; nt < 8; nt++) {
                int ch = (nt < 4) ? (cA + nt) : (cB + nt - 4);
                float ev = c_[nt][rs * 2] + sbe[ch];
                float mv = c_[nt][rs * 2 + 1] + sbm[ch];
                p[nt] = __expf(fmaf(mv, qa[nt] - ka[nt], ev));
                pv[nt] = p[nt] * va[nt];
            }
            float* drow = g_den + (size_t)d * 128;
            float* hrow = g_h + (size_t)d * 128;
            atomicAdd((float4*)(drow + cA), make_float4(p[0], p[1], p[2], p[3]));
            atomicAdd((float4*)(drow + cB), make_float4(p[4], p[5], p[6], p[7]));
            atomicAdd((float4*)(hrow + cA), make_float4(pv[0], pv[1], pv[2], pv[3]));
            atomicAdd((float4*)(hrow + cB), make_float4(pv[4], pv[5], pv[6], pv[7]));
        }
    }
}

// ----------------------------- final fused MLP (tf32, unchanged) -----------
__global__ __launch_bounds__(256, 1) void final_tc(
    const float* __restrict__ NF, const float* __restrict__ bf1,
    const float* __restrict__ gln, const float* __restrict__ bln,
    float* __restrict__ out) {
    extern __shared__ __align__(16) uint32_t sm[];
    uint32_t* sA = sm;
    uint32_t* sB1 = sm + 128 * PIT;
    uint32_t* sB2 = sm + 2 * 128 * PIT;
    float* smu = (float*)(sm + 3 * 128 * PIT);
    float* sinv = smu + 128;
    float* sgl = sinv + 128;
    float* sbl = sgl + 128;

    int tid = threadIdx.x, w = tid >> 5, lane = tid & 31;
    int wm = w >> 2, wn = w & 3, g = lane >> 2, t = lane & 3;

    for (int i = tid; i < 128 * 32; i += 256) {
        int r = i >> 5, c = (i & 31) * 4;
        *(uint4*)(sB1 + r * PIT + c) = *(const uint4*)(g_WtF1 + r * 128 + c);
        *(uint4*)(sB2 + r * PIT + c) = *(const uint4*)(g_WtF2g + r * 128 + c);
    }
    if (tid < 128) {
        sgl[tid] = gln[tid];
        sbl[tid] = bln[tid];
    }
    float b1c[4][2], vbc[4][2], vgc[4][2];
#pragma unroll
    for (int nt = 0; nt < 4; nt++) {
        int col = wn * 32 + nt * 8 + t * 2;
        b1c[nt][0] = __ldg(bf1 + col);   b1c[nt][1] = __ldg(bf1 + col + 1);
        vbc[nt][0] = g_vb[col];          vbc[nt][1] = g_vb[col + 1];
        vgc[nt][0] = g_vg[col];          vgc[nt][1] = g_vg[col + 1];
    }

    int srow = tid >> 1, shalf = tid & 1;
    const int nT = (NN + 127) >> 7;
    for (int tt = blockIdx.x; tt < nT; tt += gridDim.x) {
        __syncthreads();
        int base = tt << 7;
        for (int i = tid; i < 128 * 32; i += 256) {
            int r = i >> 5, c = (i & 31) * 4;
            int row = base + r;
            uint4 u = make_uint4(0u, 0u, 0u, 0u);
            if (row < NN) {
                float4 hh = *(const float4*)(g_h + (size_t)row * 128 + c);
                float4 dn = *(const float4*)(g_den + (size_t)row * 128 + c);
                float4 nf = *(const float4*)(NF + (size_t)row * 128 + c);
                u.x = rna((dn.x > 0.f ? hh.x / dn.x : 0.f) + nf.x);
                u.y = rna((dn.y > 0.f ? hh.y / dn.y : 0.f) + nf.y);
                u.z = rna((dn.z > 0.f ? hh.z / dn.z : 0.f) + nf.z);
                u.w = rna((dn.w > 0.f ? hh.w / dn.w : 0.f) + nf.w);
            }
            *(uint4*)(sA + r * PIT + c) = u;
        }
        __syncthreads();

        float c_[4][4][4];
#pragma unroll
        for (int mt = 0; mt < 4; mt++)
#pragma unroll
            for (int nt = 0; nt < 4; nt++)
#pragma unroll
                for (int i = 0; i < 4; i++) c_[mt][nt][i] = 0.f;
#pragma unroll
        for (int k0 = 0; k0 < 128; k0 += 8) {
            uint32_t a[4][4], b[4][2];
#pragma unroll
            for (int mt = 0; mt < 4; mt++) {
                int r = wm * 64 + mt * 16 + g;
                a[mt][0] = sA[r * PIT + k0 + t];
                a[mt][1] = sA[(r + 8) * PIT + k0 + t];
                a[mt][2] = sA[r * PIT + k0 + t + 4];
                a[mt][3] = sA[(r + 8) * PIT + k0 + t + 4];
            }
#pragma unroll
            for (int nt = 0; nt < 4; nt++) {
                int n = wn * 32 + nt * 8 + g;
                b[nt][0] = sB1[n * PIT + k0 + t];
                b[nt][1] = sB1[n * PIT + k0 + t + 4];
            }
#pragma unroll
            for (int mt = 0; mt < 4; mt++)
#pragma unroll
                for (int nt = 0; nt < 4; nt++) mma8(c_[mt][nt], a[mt], b[nt]);
        }
        __syncthreads();

#pragma unroll
        for (int mt = 0; mt < 4; mt++) {
            int r0 = wm * 64 + mt * 16 + g;
#pragma unroll
            for (int nt = 0; nt < 4; nt++) {
                int col = wn * 32 + nt * 8 + t * 2;
                uint2 u0, u1;
                u0.x = rna(mishf(c_[mt][nt][0] + b1c[nt][0]));
                u0.y = rna(mishf(c_[mt][nt][1] + b1c[nt][1]));
                u1.x = rna(mishf(c_[mt][nt][2] + b1c[nt][0]));
                u1.y = rna(mishf(c_[mt][nt][3] + b1c[nt][1]));
                *(uint2*)(sA + r0 * PIT + col) = u0;
                *(uint2*)(sA + (r0 + 8) * PIT + col) = u1;
            }
        }
        __syncthreads();

        {
            float s1 = 0.f, s2 = 0.f;
            const uint32_t* rp = sA + srow * PIT + shalf * 64;
#pragma unroll
            for (int i = 0; i < 16; i++) {
                uint4 uu = *(const uint4*)(rp + i * 4);
                float x0 = __uint_as_float(uu.x), x1 = __uint_as_float(uu.y);
                float x2 = __uint_as_float(uu.z), x3 = __uint_as_float(uu.w);
                s1 += x0 + x1 + x2 + x3;
                s2 += x0 * x0 + x1 * x1 + x2 * x2 + x3 * x3;
            }
            s1 += __shfl_xor_sync(0xffffffffu, s1, 1);
            s2 += __shfl_xor_sync(0xffffffffu, s2, 1);
            if (shalf == 0) {
                float mu = s1 * (1.f / 128.f);
                smu[srow] = mu;
                sinv[srow] = rsqrtf(s2 * (1.f / 128.f) - mu * mu + 1e-5f);
            }
        }
        __syncthreads();

        float c2[4][4][4];
#pragma unroll
        for (int mt = 0; mt < 4; mt++)
#pragma unroll
            for (int nt = 0; nt < 4; nt++)
#pragma unroll
                for (int i = 0; i < 4; i++) c2[mt][nt][i] = 0.f;
#pragma unroll
        for (int k0 = 0; k0 < 128; k0 += 8) {
            uint32_t a[4][4], b[4][2];
#pragma unroll
            for (int mt = 0; mt < 4; mt++) {
                int r = wm * 64 + mt * 16 + g;
                a[mt][0] = sA[r * PIT + k0 + t];
                a[mt][1] = sA[(r + 8) * PIT + k0 + t];
                a[mt][2] = sA[r * PIT + k0 + t + 4];
                a[mt][3] = sA[(r + 8) * PIT + k0 + t + 4];
            }
#pragma unroll
            for (int nt = 0; nt < 4; nt++) {
                int n = wn * 32 + nt * 8 + g;
                b[nt][0] = sB2[n * PIT + k0 + t];
                b[nt][1] = sB2[n * PIT + k0 + t + 4];
            }
#pragma unroll
            for (int mt = 0; mt < 4; mt++)
#pragma unroll
                for (int nt = 0; nt < 4; nt++) mma8(c2[mt][nt], a[mt], b[nt]);
        }
        __syncthreads();

#pragma unroll
        for (int mt = 0; mt < 4; mt++) {
            int r0 = wm * 64 + mt * 16 + g;
            float mu0 = smu[r0], iv0 = sinv[r0];
            float mu8 = smu[r0 + 8], iv8 = sinv[r0 + 8];
#pragma unroll
            for (int nt = 0; nt < 4; nt++) {
                int col = wn * 32 + nt * 8 + t * 2;
                uint2 y0, y1;
                y0.x = __float_as_uint(iv0 * c2[mt][nt][0] + vbc[nt][0] - mu0 * iv0 * vgc[nt][0]);
                y0.y = __float_as_uint(iv0 * c2[mt][nt][1] + vbc[nt][1] - mu0 * iv0 * vgc[nt][1]);
                y1.x = __float_as_uint(iv8 * c2[mt][nt][2] + vbc[nt][0] - mu8 * iv8 * vgc[nt][0]);
                y1.y = __float_as_uint(iv8 * c2[mt][nt][3] + vbc[nt][1] - mu8 * iv8 * vgc[nt][1]);
                *(uint2*)(sA + r0 * PIT + col) = y0;
                *(uint2*)(sA + (r0 + 8) * PIT + col) = y1;
            }
        }
        __syncthreads();

        {
            float s1 = 0.f, s2 = 0.f;
            const uint32_t* rp = sA + srow * PIT + shalf * 64;
#pragma unroll
            for (int i = 0; i < 16; i++) {
                uint4 uu = *(const uint4*)(rp + i * 4);
                float x0 = __uint_as_float(uu.x), x1 = __uint_as_float(uu.y);
                float x2 = __uint_as_float(uu.z), x3 = __uint_as_float(uu.w);
                s1 += x0 + x1 + x2 + x3;
                s2 += x0 * x0 + x1 * x1 + x2 * x2 + x3 * x3;
            }
            s1 += __shfl_xor_sync(0xffffffffu, s1, 1);
            s2 += __shfl_xor_sync(0xffffffffu, s2, 1);
            if (shalf == 0) {
                float mu = s1 * (1.f / 128.f);
                smu[srow] = mu;
                sinv[srow] = rsqrtf(s2 * (1.f / 128.f) - mu * mu + 1e-5f);
            }
        }
        __syncthreads();

        {
            int row = base + srow;
            if (row < NN) {
                float mu = smu[srow], iv = sinv[srow];
                const uint32_t* rp = sA + srow * PIT + shalf * 64;
#pragma unroll
                for (int i = 0; i < 16; i++) {
                    int col = shalf * 64 + i * 4;
                    uint4 uu = *(const uint4*)(rp + i * 4);
                    float4 o;
                    o.x = (__uint_as_float(uu.x) - mu) * iv * sgl[col + 0] + sbl[col + 0];
                    o.y = (__uint_as_float(uu.y) - mu) * iv * sgl[col + 1] + sbl[col + 1];
                    o.z = (__uint_as_float(uu.z) - mu) * iv * sgl[col + 2] + sbl[col + 2];
                    o.w = (__uint_as_float(uu.w) - mu) * iv * sgl[col + 3] + sbl[col + 3];
                    *(float4*)(out + (size_t)row * 128 + col) = o;
                }
            }
        }
    }
}

// ---------------------------------------------------------------------------
extern "C" void kernel_launch(void* const* d_in, const int* in_sizes, int n_in,
                              void* d_out, int out_size) {
    const float* node_feats = (const float*)d_in[0];
    const float* edge_feats = (const float*)d_in[1];
    const int* src = (const int*)d_in[2];
    const int* dst = (const int*)d_in[3];
    const float* Wq = (const float*)d_in[4];
    const float* bq = (const float*)d_in[5];
    const float* Wk = (const float*)d_in[6];
    const float* bk = (const float*)d_in[7];
    const float* Wv = (const float*)d_in[8];
    const float* bv = (const float*)d_in[9];
    const float* We = (const float*)d_in[10];
    const float* be = (const float*)d_in[11];
    const float* Wm = (const float*)d_in[12];
    const float* bm = (const float*)d_in[13];
    const float* Wf1 = (const float*)d_in[14];
    const float* bf1 = (const float*)d_in[15];
    const float* g_f = (const float*)d_in[16];
    const float* b_f = (const float*)d_in[17];
    const float* Wf2 = (const float*)d_in[18];
    const float* bf2 = (const float*)d_in[19];
    const float* g_ln = (const float*)d_in[20];
    const float* b_ln = (const float*)d_in[21];
    float* out = (float*)d_out;

    void *pden, *ph, *pq, *pk, *pv;
    cudaGetSymbolAddress(&pden, g_den);
    cudaGetSymbolAddress(&ph, g_h);
    cudaGetSymbolAddress(&pq, g_qh);
    cudaGetSymbolAddress(&pk, g_kh);
    cudaGetSymbolAddress(&pv, g_vh);

    const size_t QKV_SMEM = (size_t)(64 * ABLK + 384 * BBLK + 16384 + 384) * 4;   // 202240
    const size_t EDGE_SMEM = (size_t)(64 * ABLK + 256 * BBLK + 16384 + 256) * 4;  // 167936
    const size_t FIN_SMEM = (size_t)(3 * 128 * PIT + 512) * 4;                    // 204800
    cudaFuncSetAttribute(qkv_tc, cudaFuncAttributeMaxDynamicSharedMemorySize, (int)QKV_SMEM);
    cudaFuncSetAttribute(edge_tc, cudaFuncAttributeMaxDynamicSharedMemorySize, (int)EDGE_SMEM);
    cudaFuncSetAttribute(final_tc, cudaFuncAttributeMaxDynamicSharedMemorySize, (int)FIN_SMEM);

    cudaMemsetAsync(pden, 0, (size_t)NN * 128 * sizeof(float), 0);
    cudaMemsetAsync(ph, 0, (size_t)NN * 128 * sizeof(float), 0);

    prep_T<<<64, 128>>>(Wq, Wk, Wv, We, Wm, Wf1, Wf2, g_f);
    prep_V<<<1, 128>>>(Wf2, b_f, g_f, bf2);

    qkv_tc<<<148, 1024, QKV_SMEM>>>(node_feats, bq, bk, bv, (uint32_t*)pq, (uint32_t*)pk,
                                    (uint32_t*)pv);

    edge_tc<<<148, 1024, EDGE_SMEM>>>(edge_feats, be, bm, src, dst, out + (size_t)NN * 128);

    final_tc<<<148, 256, FIN_SMEM>>>(node_feats, bf1, g_ln, b_ln, out);
}

// round 13
// speedup vs baseline: 1.2938x; 1.1666x over previous
#include <cuda_runtime.h>
#include <cuda_fp16.h>
#include <cstdint>
#include <math.h>

#define NN 50000
#define NE 800000

// fp16 fragment-major strides (32-bit words)
#define ABLK 132  // A block (16r x 16k): 32 lanes x 4 words, pad 128->132
#define BBLK 66   // B block (8n x 16k): 32 lanes x 2 words, pad 64->66
#define PIT 132   // legacy tf32 pitch for final_tc

// ----------------------------- scratch globals -----------------------------
__device__ uint32_t g_qh[NN * 64];  // q rows, fp16 half2 words
__device__ uint32_t g_kh[NN * 64];
__device__ uint32_t g_vh[NN * 64];
__device__ float g_den[NN * 128];
__device__ float g_h[NN * 128];

__device__ uint32_t g_WhQKV[384 * 128];  // packed [Wq|Wk|Wv], fp16 frag-major
__device__ uint32_t g_WhEM[256 * 128];   // channel-permuted [We|Wm], fp16 frag-major
__device__ uint32_t g_WtF1[128 * 128];   // tf32 [n][k] for final_tc
__device__ uint32_t g_WtF2g[128 * 128];
__device__ float g_vb[128];
__device__ float g_vg[128];

// ----------------------------- helpers -------------------------------------
__device__ __forceinline__ uint32_t rna(float x) {
    uint32_t r;
    asm("cvt.rna.tf32.f32 %0, %1;" : "=r"(r) : "f"(x));
    return r;
}
__device__ __forceinline__ uint32_t pk2(float a, float b) {
    __half2 h = __floats2half2_rn(a, b);
    return *reinterpret_cast<uint32_t*>(&h);
}
__device__ __forceinline__ void mma16(float* c, const uint32_t* a, const uint32_t* b) {
    asm volatile(
        "mma.sync.aligned.m16n8k16.row.col.f32.f16.f16.f32 "
        "{%0,%1,%2,%3}, {%4,%5,%6,%7}, {%8,%9}, {%0,%1,%2,%3};"
        : "+f"(c[0]), "+f"(c[1]), "+f"(c[2]), "+f"(c[3])
        : "r"(a[0]), "r"(a[1]), "r"(a[2]), "r"(a[3]), "r"(b[0]), "r"(b[1]));
}
__device__ __forceinline__ void mma8(float* c, const uint32_t* a, const uint32_t* b) {
    asm volatile(
        "mma.sync.aligned.m16n8k8.row.col.f32.tf32.tf32.f32 "
        "{%0,%1,%2,%3}, {%4,%5,%6,%7}, {%8,%9}, {%0,%1,%2,%3};"
        : "+f"(c[0]), "+f"(c[1]), "+f"(c[2]), "+f"(c[3])
        : "r"(a[0]), "r"(a[1]), "r"(a[2]), "r"(a[3]), "r"(b[0]), "r"(b[1]));
}
__device__ __forceinline__ float mishf(float x) {
    float sp = (x > 20.f) ? x : log1pf(__expf(x));
    return x * tanhf(sp);
}
__device__ __forceinline__ uint64_t mkpol_ef() {
    uint64_t p;
    asm("createpolicy.fractional.L2::evict_first.b64 %0, 1.0;" : "=l"(p));
    return p;
}
__device__ __forceinline__ void cpasync16_ef(uint32_t saddr, const void* g, uint64_t pol) {
    asm volatile("cp.async.cg.shared.global.L2::cache_hint [%0], [%1], 16, %2;"
                 ::"r"(saddr), "l"(g), "l"(pol));
}
#define CP_COMMIT() asm volatile("cp.async.commit_group;" ::: "memory")
#define CP_WAIT0() asm volatile("cp.async.wait_group 0;" ::: "memory")

// fp16 frag-major gmem word index for B value pair (n, k2), k2 = k>>1
__device__ __forceinline__ int fidx16(int n, int k2) {
    return (((n >> 3) << 3) + (k2 >> 3)) * 64 + (((((n & 7) << 2) | (k2 & 3))) << 1) +
           ((k2 >> 2) & 1);
}
// fp16 frag-major smem word index for A halves (r, c), c multiple of 4
__device__ __forceinline__ int aidx16(int r, int c) {
    return ABLK * (((r >> 4) << 3) + (c >> 4)) + ((((r & 7) << 2) | ((c >> 1) & 3)) << 2) +
           ((r >> 3) & 1) + (((c >> 3) & 1) << 1);
}

// ----------------------------- prep kernels --------------------------------
__global__ void prep_T(const float* __restrict__ Wq, const float* __restrict__ Wk,
                       const float* __restrict__ Wv, const float* __restrict__ We,
                       const float* __restrict__ Wm, const float* __restrict__ Wf1,
                       const float* __restrict__ Wf2, const float* __restrict__ gf) {
    int k2 = blockIdx.x, n = threadIdx.x;
    int k0 = k2 * 2, k1 = k0 + 1;
    g_WhQKV[fidx16(n, k2)] = pk2(Wq[k0 * 128 + n], Wq[k1 * 128 + n]);
    g_WhQKV[fidx16(128 + n, k2)] = pk2(Wk[k0 * 128 + n], Wk[k1 * 128 + n]);
    g_WhQKV[fidx16(256 + n, k2)] = pk2(Wv[k0 * 128 + n], Wv[k1 * 128 + n]);
    g_WtF1[n * 128 + k0] = rna(Wf1[k0 * 128 + n]);
    g_WtF1[n * 128 + k1] = rna(Wf1[k1 * 128 + n]);
    g_WtF2g[n * 128 + k0] = rna(gf[k0] * Wf2[k0 * 128 + n]);
    g_WtF2g[n * 128 + k1] = rna(gf[k1] * Wf2[k1 * 128 + n]);
    // EM permutation: GEMM col j -> channel. Thread (wn,t) owns quads
    // cA = wn*32 + t*4 (nt 0..3) and cB = cA+16 (nt 4..7) -> coalesced REDs.
#pragma unroll
    for (int jj = 0; jj < 2; jj++) {
        int j = n + jj * 128;
        int wn = j >> 6, wi = j & 63, nt = wi >> 3, rem = wi & 7, tt = rem >> 1, par = rem & 1;
        int ch = wn * 32 + ((nt >> 2) << 4) + tt * 4 + (nt & 3);
        const float* W = par ? Wm : We;
        g_WhEM[fidx16(j, k2)] = pk2(W[k0 * 128 + ch], W[k1 * 128 + ch]);
    }
}

__global__ void prep_V(const float* __restrict__ Wf2, const float* __restrict__ bf,
                       const float* __restrict__ gf, const float* __restrict__ bf2) {
    int n = threadIdx.x;
    float a = 0.f, b = 0.f;
    for (int k = 0; k < 128; k++) {
        float w = Wf2[k * 128 + n];
        a = fmaf(bf[k], w, a);
        b = fmaf(gf[k], w, b);
    }
    g_vb[n] = bf2[n] + a;
    g_vg[n] = b;
}

// ----------------------------- fused QKV linear -----------------------------
// q/k/v = NF @ [Wq|Wk|Wv] + b, outputs stored fp16 (half2 words).
__global__ __launch_bounds__(1024, 1) void qkv_tc(
    const float* __restrict__ X,
    const float* __restrict__ bq, const float* __restrict__ bk,
    const float* __restrict__ bv,
    uint32_t* __restrict__ Yq, uint32_t* __restrict__ Yk, uint32_t* __restrict__ Yv) {
    extern __shared__ __align__(16) uint32_t sm[];
    uint32_t* sA = sm;                       // 8448
    uint32_t* sB = sm + 64 * ABLK;           // 25344
    uint32_t* stage = sB + 384 * BBLK;       // 16384
    float* sbias = (float*)(stage + 16384);  // 384

    int tid = threadIdx.x, w = tid >> 5, lane = tid & 31;
    int wm = w >> 2, wn = w & 3, g = lane >> 2, t = lane & 3;
    uint32_t stage_a = (uint32_t)__cvta_generic_to_shared(stage);
    uint64_t pol = mkpol_ef();

    for (int i = tid; i < 384 * 32; i += 1024) {
        int blk = i >> 5, l = i & 31;
        *(uint2*)(sB + blk * BBLK + l * 2) = *(const uint2*)(g_WhQKV + blk * 64 + l * 2);
    }
    if (tid < 128) {
        sbias[tid] = bq[tid];
        sbias[128 + tid] = bk[tid];
        sbias[256 + tid] = bv[tid];
    }

    int r0 = tid >> 5, c0 = (tid & 31) * 4;
    const int M = NN;
    int nT = (M + 127) >> 7;
    int tt = blockIdx.x;
    if (tt < nT) {
        int base = tt << 7;
#pragma unroll
        for (int ii = 0; ii < 4; ii++) {
            int r = r0 + ii * 32;
            int rowc = min(base + r, M - 1);
            cpasync16_ef(stage_a + (uint32_t)(r * 128 + c0) * 4, X + (size_t)rowc * 128 + c0, pol);
        }
        CP_COMMIT();
    }

    for (; tt < nT; tt += gridDim.x) {
        int base = tt << 7;
        CP_WAIT0();
        __syncthreads();
#pragma unroll
        for (int ii = 0; ii < 4; ii++) {
            int r = r0 + ii * 32;
            uint4 raw = *(const uint4*)(stage + r * 128 + c0);
            int w0 = aidx16(r, c0);
            sA[w0] = pk2(__uint_as_float(raw.x), __uint_as_float(raw.y));
            sA[w0 + 4] = pk2(__uint_as_float(raw.z), __uint_as_float(raw.w));
        }
        __syncthreads();
        int tn = tt + gridDim.x;
        if (tn < nT) {
            int nb = tn << 7;
#pragma unroll
            for (int ii = 0; ii < 4; ii++) {
                int r = r0 + ii * 32;
                int rowc = min(nb + r, M - 1);
                cpasync16_ef(stage_a + (uint32_t)(r * 128 + c0) * 4, X + (size_t)rowc * 128 + c0,
                             pol);
            }
            CP_COMMIT();
        }

        int row = base + wm * 16 + g;
#pragma unroll
        for (int sel = 0; sel < 3; sel++) {
            uint32_t* Y = sel == 0 ? Yq : sel == 1 ? Yk : Yv;
            float c_[4][4];
#pragma unroll
            for (int nt = 0; nt < 4; nt++)
#pragma unroll
                for (int i = 0; i < 4; i++) c_[nt][i] = 0.f;
#pragma unroll
            for (int ks = 0; ks < 8; ks++) {
                uint32_t a[4];
                *(uint4*)a = *(const uint4*)(sA + ABLK * (wm * 8 + ks) + lane * 4);
#pragma unroll
                for (int nt = 0; nt < 4; nt++) {
                    uint32_t b[2];
                    int blk = (sel * 16 + wn * 4 + nt) * 8 + ks;
                    *(uint2*)b = *(const uint2*)(sB + BBLK * blk + lane * 2);
                    mma16(c_[nt], a, b);
                }
            }
#pragma unroll
            for (int nt = 0; nt < 4; nt++) {
                int col = wn * 32 + nt * 8 + t * 2;
                float b0 = sbias[sel * 128 + col], b1 = sbias[sel * 128 + col + 1];
                if (row < M)
                    Y[(size_t)row * 64 + (col >> 1)] = pk2(c_[nt][0] + b0, c_[nt][1] + b1);
                if (row + 8 < M)
                    Y[(size_t)(row + 8) * 64 + (col >> 1)] = pk2(c_[nt][2] + b0, c_[nt][3] + b1);
            }
        }
    }
}

// ----------------------------- fused edge pass ------------------------------
// 512 threads, 64-edge tiles, 2 CTAs/SM: one CTA's MMA/RED phase overlaps the
// other's EF loads and barrier waits. EF loaded via __ldcs (no stage buffer).
// [e|m](perm) = EF @ WhEM ; p = exp((m+bm)*(q[src]-k[dst]) + e+be)
// den[dst] += p ; h[dst] += p*v[src]. Streams EF -> outE. Coalesced REDs.
__global__ __launch_bounds__(512) void edge_tc(
    const float* __restrict__ EF, const float* __restrict__ be,
    const float* __restrict__ bm, const int* __restrict__ src,
    const int* __restrict__ dst, float* __restrict__ outE) {
    extern __shared__ __align__(16) uint32_t sm[];
    uint32_t* sA = sm;               // 32 blocks * ABLK = 4224 words
    uint32_t* sB = sm + 32 * ABLK;   // 256 blocks * BBLK = 16896 words
    float* sbe = (float*)(sB + 256 * BBLK);
    float* sbm = sbe + 128;

    int tid = threadIdx.x, w = tid >> 5, lane = tid & 31;
    int wm = w >> 2, wn = w & 3, g = lane >> 2, t = lane & 3;
    int cA = wn * 32 + t * 4;
    int cB = cA + 16;
    int cAw = cA >> 1, cBw = cB >> 1;

    for (int i = tid; i < 256 * 32; i += 512) {
        int blk = i >> 5, l = i & 31;
        *(uint2*)(sB + blk * BBLK + l * 2) = *(const uint2*)(g_WhEM + blk * 64 + l * 2);
    }
    if (tid < 128) {
        sbe[tid] = be[tid];
        sbm[tid] = bm[tid];
    }

    int rr = tid >> 3;           // row 0..63
    int c8 = (tid & 7) * 4;      // float4 col group base (floats): +ii*32
    int rl0 = wm * 16 + g, rl1 = rl0 + 8;

    const int nT = NE / 64;  // 12500 exact
    for (int tt = blockIdx.x; tt < nT; tt += gridDim.x) {
        int base = tt << 6;
        int s0 = __ldg(src + base + rl0), d0 = __ldg(dst + base + rl0);
        int s1 = __ldg(src + base + rl1), d1 = __ldg(dst + base + rl1);
        // load EF slice (streaming), convert to fp16 frag-major, emit passthrough
        float4 x0 = __ldcs((const float4*)(EF + (size_t)(base + rr) * 128 + c8));
        float4 x1 = __ldcs((const float4*)(EF + (size_t)(base + rr) * 128 + c8 + 32));
        float4 x2 = __ldcs((const float4*)(EF + (size_t)(base + rr) * 128 + c8 + 64));
        float4 x3 = __ldcs((const float4*)(EF + (size_t)(base + rr) * 128 + c8 + 96));
        __syncthreads();  // all warps done reading sA from prior tile
        {
            float4 xs[4] = {x0, x1, x2, x3};
#pragma unroll
            for (int ii = 0; ii < 4; ii++) {
                int c = c8 + ii * 32;
                __stcs((float4*)(outE + (size_t)(base + rr) * 128 + c), xs[ii]);
                int w0 = aidx16(rr, c);
                sA[w0] = pk2(xs[ii].x, xs[ii].y);
                sA[w0 + 4] = pk2(xs[ii].z, xs[ii].w);
            }
        }
        __syncthreads();  // sA ready

        float c_[8][4];
#pragma unroll
        for (int nt = 0; nt < 8; nt++)
#pragma unroll
            for (int i = 0; i < 4; i++) c_[nt][i] = 0.f;
#pragma unroll
        for (int ks = 0; ks < 8; ks++) {
            uint32_t a[4];
            *(uint4*)a = *(const uint4*)(sA + ABLK * (wm * 8 + ks) + lane * 4);
#pragma unroll
            for (int nt = 0; nt < 8; nt++) {
                uint32_t b[2];
                *(uint2*)b = *(const uint2*)(sB + BBLK * ((wn * 8 + nt) * 8 + ks) + lane * 2);
                mma16(c_[nt], a, b);
            }
        }

        // epilogue: thread owns channels cA..cA+3 (nt 0..3), cB..cB+3 (nt 4..7)
#pragma unroll
        for (int rs = 0; rs < 2; rs++) {
            int s = rs ? s1 : s0, d = rs ? d1 : d0;
            uint2 qA = __ldg((const uint2*)(g_qh + (size_t)s * 64 + cAw));
            uint2 qB = __ldg((const uint2*)(g_qh + (size_t)s * 64 + cBw));
            uint2 kA = __ldg((const uint2*)(g_kh + (size_t)d * 64 + cAw));
            uint2 kB = __ldg((const uint2*)(g_kh + (size_t)d * 64 + cBw));
            uint2 vA = __ldg((const uint2*)(g_vh + (size_t)s * 64 + cAw));
            uint2 vB = __ldg((const uint2*)(g_vh + (size_t)s * 64 + cBw));
            float qa[8], ka[8], va[8];
            {
                float2 f;
                f = __half22float2(*(const __half2*)&qA.x); qa[0] = f.x; qa[1] = f.y;
                f = __half22float2(*(const __half2*)&qA.y); qa[2] = f.x; qa[3] = f.y;
                f = __half22float2(*(const __half2*)&qB.x); qa[4] = f.x; qa[5] = f.y;
                f = __half22float2(*(const __half2*)&qB.y); qa[6] = f.x; qa[7] = f.y;
                f = __half22float2(*(const __half2*)&kA.x); ka[0] = f.x; ka[1] = f.y;
                f = __half22float2(*(const __half2*)&kA.y); ka[2] = f.x; ka[3] = f.y;
                f = __half22float2(*(const __half2*)&kB.x); ka[4] = f.x; ka[5] = f.y;
                f = __half22float2(*(const __half2*)&kB.y); ka[6] = f.x; ka[7] = f.y;
                f = __half22float2(*(const __half2*)&vA.x); va[0] = f.x; va[1] = f.y;
                f = __half22float2(*(const __half2*)&vA.y); va[2] = f.x; va[3] = f.y;
                f = __half22float2(*(const __half2*)&vB.x); va[4] = f.x; va[5] = f.y;
                f = __half22float2(*(const __half2*)&vB.y); va[6] = f.x; va[7] = f.y;
            }
            float p[8], pv[8];
#pragma unroll
            for (int nt = 0; nt < 8; nt++) {
                int ch = (nt < 4) ? (cA + nt) : (cB + nt - 4);
                float ev = c_[nt][rs * 2] + sbe[ch];
                float mv = c_[nt][rs * 2 + 1] + sbm[ch];
                p[nt] = __expf(fmaf(mv, qa[nt] - ka[nt], ev));
                pv[nt] = p[nt] * va[nt];
            }
            float* drow = g_den + (size_t)d * 128;
            float* hrow = g_h + (size_t)d * 128;
            atomicAdd((float4*)(drow + cA), make_float4(p[0], p[1], p[2], p[3]));
            atomicAdd((float4*)(drow + cB), make_float4(p[4], p[5], p[6], p[7]));
            atomicAdd((float4*)(hrow + cA), make_float4(pv[0], pv[1], pv[2], pv[3]));
            atomicAdd((float4*)(hrow + cB), make_float4(pv[4], pv[5], pv[6], pv[7]));
        }
    }
}

// ----------------------------- final fused MLP (tf32, unchanged) -----------
__global__ __launch_bounds__(256, 1) void final_tc(
    const float* __restrict__ NF, const float* __restrict__ bf1,
    const float* __restrict__ gln, const float* __restrict__ bln,
    float* __restrict__ out) {
    extern __shared__ __align__(16) uint32_t sm[];
    uint32_t* sA = sm;
    uint32_t* sB1 = sm + 128 * PIT;
    uint32_t* sB2 = sm + 2 * 128 * PIT;
    float* smu = (float*)(sm + 3 * 128 * PIT);
    float* sinv = smu + 128;
    float* sgl = sinv + 128;
    float* sbl = sgl + 128;

    int tid = threadIdx.x, w = tid >> 5, lane = tid & 31;
    int wm = w >> 2, wn = w & 3, g = lane >> 2, t = lane & 3;

    for (int i = tid; i < 128 * 32; i += 256) {
        int r = i >> 5, c = (i & 31) * 4;
        *(uint4*)(sB1 + r * PIT + c) = *(const uint4*)(g_WtF1 + r * 128 + c);
        *(uint4*)(sB2 + r * PIT + c) = *(const uint4*)(g_WtF2g + r * 128 + c);
    }
    if (tid < 128) {
        sgl[tid] = gln[tid];
        sbl[tid] = bln[tid];
    }
    float b1c[4][2], vbc[4][2], vgc[4][2];
#pragma unroll
    for (int nt = 0; nt < 4; nt++) {
        int col = wn * 32 + nt * 8 + t * 2;
        b1c[nt][0] = __ldg(bf1 + col);   b1c[nt][1] = __ldg(bf1 + col + 1);
        vbc[nt][0] = g_vb[col];          vbc[nt][1] = g_vb[col + 1];
        vgc[nt][0] = g_vg[col];          vgc[nt][1] = g_vg[col + 1];
    }

    int srow = tid >> 1, shalf = tid & 1;
    const int nT = (NN + 127) >> 7;
    for (int tt = blockIdx.x; tt < nT; tt += gridDim.x) {
        __syncthreads();
        int base = tt << 7;
        for (int i = tid; i < 128 * 32; i += 256) {
            int r = i >> 5, c = (i & 31) * 4;
            int row = base + r;
            uint4 u = make_uint4(0u, 0u, 0u, 0u);
            if (row < NN) {
                float4 hh = *(const float4*)(g_h + (size_t)row * 128 + c);
                float4 dn = *(const float4*)(g_den + (size_t)row * 128 + c);
                float4 nf = *(const float4*)(NF + (size_t)row * 128 + c);
                u.x = rna((dn.x > 0.f ? hh.x / dn.x : 0.f) + nf.x);
                u.y = rna((dn.y > 0.f ? hh.y / dn.y : 0.f) + nf.y);
                u.z = rna((dn.z > 0.f ? hh.z / dn.z : 0.f) + nf.z);
                u.w = rna((dn.w > 0.f ? hh.w / dn.w : 0.f) + nf.w);
            }
            *(uint4*)(sA + r * PIT + c) = u;
        }
        __syncthreads();

        float c_[4][4][4];
#pragma unroll
        for (int mt = 0; mt < 4; mt++)
#pragma unroll
            for (int nt = 0; nt < 4; nt++)
#pragma unroll
                for (int i = 0; i < 4; i++) c_[mt][nt][i] = 0.f;
#pragma unroll
        for (int k0 = 0; k0 < 128; k0 += 8) {
            uint32_t a[4][4], b[4][2];
#pragma unroll
            for (int mt = 0; mt < 4; mt++) {
                int r = wm * 64 + mt * 16 + g;
                a[mt][0] = sA[r * PIT + k0 + t];
                a[mt][1] = sA[(r + 8) * PIT + k0 + t];
                a[mt][2] = sA[r * PIT + k0 + t + 4];
                a[mt][3] = sA[(r + 8) * PIT + k0 + t + 4];
            }
#pragma unroll
            for (int nt = 0; nt < 4; nt++) {
                int n = wn * 32 + nt * 8 + g;
                b[nt][0] = sB1[n * PIT + k0 + t];
                b[nt][1] = sB1[n * PIT + k0 + t + 4];
            }
#pragma unroll
            for (int mt = 0; mt < 4; mt++)
#pragma unroll
                for (int nt = 0; nt < 4; nt++) mma8(c_[mt][nt], a[mt], b[nt]);
        }
        __syncthreads();

#pragma unroll
        for (int mt = 0; mt < 4; mt++) {
            int r0 = wm * 64 + mt * 16 + g;
#pragma unroll
            for (int nt = 0; nt < 4; nt++) {
                int col = wn * 32 + nt * 8 + t * 2;
                uint2 u0, u1;
                u0.x = rna(mishf(c_[mt][nt][0] + b1c[nt][0]));
                u0.y = rna(mishf(c_[mt][nt][1] + b1c[nt][1]));
                u1.x = rna(mishf(c_[mt][nt][2] + b1c[nt][0]));
                u1.y = rna(mishf(c_[mt][nt][3] + b1c[nt][1]));
                *(uint2*)(sA + r0 * PIT + col) = u0;
                *(uint2*)(sA + (r0 + 8) * PIT + col) = u1;
            }
        }
        __syncthreads();

        {
            float s1 = 0.f, s2 = 0.f;
            const uint32_t* rp = sA + srow * PIT + shalf * 64;
#pragma unroll
            for (int i = 0; i < 16; i++) {
                uint4 uu = *(const uint4*)(rp + i * 4);
                float x0 = __uint_as_float(uu.x), x1 = __uint_as_float(uu.y);
                float x2 = __uint_as_float(uu.z), x3 = __uint_as_float(uu.w);
                s1 += x0 + x1 + x2 + x3;
                s2 += x0 * x0 + x1 * x1 + x2 * x2 + x3 * x3;
            }
            s1 += __shfl_xor_sync(0xffffffffu, s1, 1);
            s2 += __shfl_xor_sync(0xffffffffu, s2, 1);
            if (shalf == 0) {
                float mu = s1 * (1.f / 128.f);
                smu[srow] = mu;
                sinv[srow] = rsqrtf(s2 * (1.f / 128.f) - mu * mu + 1e-5f);
            }
        }
        __syncthreads();

        float c2[4][4][4];
#pragma unroll
        for (int mt = 0; mt < 4; mt++)
#pragma unroll
            for (int nt = 0; nt < 4; nt++)
#pragma unroll
                for (int i = 0; i < 4; i++) c2[mt][nt][i] = 0.f;
#pragma unroll
        for (int k0 = 0; k0 < 128; k0 += 8) {
            uint32_t a[4][4], b[4][2];
#pragma unroll
            for (int mt = 0; mt < 4; mt++) {
                int r = wm * 64 + mt * 16 + g;
                a[mt][0] = sA[r * PIT + k0 + t];
                a[mt][1] = sA[(r + 8) * PIT + k0 + t];
                a[mt][2] = sA[r * PIT + k0 + t + 4];
                a[mt][3] = sA[(r + 8) * PIT + k0 + t + 4];
            }
#pragma unroll
            for (int nt = 0; nt < 4; nt++) {
                int n = wn * 32 + nt * 8 + g;
                b[nt][0] = sB2[n * PIT + k0 + t];
                b[nt][1] = sB2[n * PIT + k0 + t + 4];
            }
#pragma unroll
            for (int mt = 0; mt < 4; mt++)
#pragma unroll
                for (int nt = 0; nt < 4; nt++) mma8(c2[mt][nt], a[mt], b[nt]);
        }
        __syncthreads();

#pragma unroll
        for (int mt = 0; mt < 4; mt++) {
            int r0 = wm * 64 + mt * 16 + g;
            float mu0 = smu[r0], iv0 = sinv[r0];
            float mu8 = smu[r0 + 8], iv8 = sinv[r0 + 8];
#pragma unroll
            for (int nt = 0; nt < 4; nt++) {
                int col = wn * 32 + nt * 8 + t * 2;
                uint2 y0, y1;
                y0.x = __float_as_uint(iv0 * c2[mt][nt][0] + vbc[nt][0] - mu0 * iv0 * vgc[nt][0]);
                y0.y = __float_as_uint(iv0 * c2[mt][nt][1] + vbc[nt][1] - mu0 * iv0 * vgc[nt][1]);
                y1.x = __float_as_uint(iv8 * c2[mt][nt][2] + vbc[nt][0] - mu8 * iv8 * vgc[nt][0]);
                y1.y = __float_as_uint(iv8 * c2[mt][nt][3] + vbc[nt][1] - mu8 * iv8 * vgc[nt][1]);
                *(uint2*)(sA + r0 * PIT + col) = y0;
                *(uint2*)(sA + (r0 + 8) * PIT + col) = y1;
            }
        }
        __syncthreads();

        {
            float s1 = 0.f, s2 = 0.f;
            const uint32_t* rp = sA + srow * PIT + shalf * 64;
#pragma unroll
            for (int i = 0; i < 16; i++) {
                uint4 uu = *(const uint4*)(rp + i * 4);
                float x0 = __uint_as_float(uu.x), x1 = __uint_as_float(uu.y);
                float x2 = __uint_as_float(uu.z), x3 = __uint_as_float(uu.w);
                s1 += x0 + x1 + x2 + x3;
                s2 += x0 * x0 + x1 * x1 + x2 * x2 + x3 * x3;
            }
            s1 += __shfl_xor_sync(0xffffffffu, s1, 1);
            s2 += __shfl_xor_sync(0xffffffffu, s2, 1);
            if (shalf == 0) {
                float mu = s1 * (1.f / 128.f);
                smu[srow] = mu;
                sinv[srow] = rsqrtf(s2 * (1.f / 128.f) - mu * mu + 1e-5f);
            }
        }
        __syncthreads();

        {
            int row = base + srow;
            if (row < NN) {
                float mu = smu[srow], iv = sinv[srow];
                const uint32_t* rp = sA + srow * PIT + shalf * 64;
#pragma unroll
                for (int i = 0; i < 16; i++) {
                    int col = shalf * 64 + i * 4;
                    uint4 uu = *(const uint4*)(rp + i * 4);
                    float4 o;
                    o.x = (__uint_as_float(uu.x) - mu) * iv * sgl[col + 0] + sbl[col + 0];
                    o.y = (__uint_as_float(uu.y) - mu) * iv * sgl[col + 1] + sbl[col + 1];
                    o.z = (__uint_as_float(uu.z) - mu) * iv * sgl[col + 2] + sbl[col + 2];
                    o.w = (__uint_as_float(uu.w) - mu) * iv * sgl[col + 3] + sbl[col + 3];
                    *(float4*)(out + (size_t)row * 128 + col) = o;
                }
            }
        }
    }
}

// ---------------------------------------------------------------------------
extern "C" void kernel_launch(void* const* d_in, const int* in_sizes, int n_in,
                              void* d_out, int out_size) {
    const float* node_feats = (const float*)d_in[0];
    const float* edge_feats = (const float*)d_in[1];
    const int* src = (const int*)d_in[2];
    const int* dst = (const int*)d_in[3];
    const float* Wq = (const float*)d_in[4];
    const float* bq = (const float*)d_in[5];
    const float* Wk = (const float*)d_in[6];
    const float* bk = (const float*)d_in[7];
    const float* Wv = (const float*)d_in[8];
    const float* bv = (const float*)d_in[9];
    const float* We = (const float*)d_in[10];
    const float* be = (const float*)d_in[11];
    const float* Wm = (const float*)d_in[12];
    const float* bm = (const float*)d_in[13];
    const float* Wf1 = (const float*)d_in[14];
    const float* bf1 = (const float*)d_in[15];
    const float* g_f = (const float*)d_in[16];
    const float* b_f = (const float*)d_in[17];
    const float* Wf2 = (const float*)d_in[18];
    const float* bf2 = (const float*)d_in[19];
    const float* g_ln = (const float*)d_in[20];
    const float* b_ln = (const float*)d_in[21];
    float* out = (float*)d_out;

    void *pden, *ph, *pq, *pk, *pv;
    cudaGetSymbolAddress(&pden, g_den);
    cudaGetSymbolAddress(&ph, g_h);
    cudaGetSymbolAddress(&pq, g_qh);
    cudaGetSymbolAddress(&pk, g_kh);
    cudaGetSymbolAddress(&pv, g_vh);

    const size_t QKV_SMEM = (size_t)(64 * ABLK + 384 * BBLK + 16384 + 384) * 4;  // 202240
    const size_t EDGE_SMEM = (size_t)(32 * ABLK + 256 * BBLK + 256) * 4;         // 85504
    const size_t FIN_SMEM = (size_t)(3 * 128 * PIT + 512) * 4;                   // 204800
    cudaFuncSetAttribute(qkv_tc, cudaFuncAttributeMaxDynamicSharedMemorySize, (int)QKV_SMEM);
    cudaFuncSetAttribute(edge_tc, cudaFuncAttributeMaxDynamicSharedMemorySize, (int)EDGE_SMEM);
    cudaFuncSetAttribute(final_tc, cudaFuncAttributeMaxDynamicSharedMemorySize, (int)FIN_SMEM);

    cudaMemsetAsync(pden, 0, (size_t)NN * 128 * sizeof(float), 0);
    cudaMemsetAsync(ph, 0, (size_t)NN * 128 * sizeof(float), 0);

    prep_T<<<64, 128>>>(Wq, Wk, Wv, We, Wm, Wf1, Wf2, g_f);
    prep_V<<<1, 128>>>(Wf2, b_f, g_f, bf2);

    qkv_tc<<<148, 1024, QKV_SMEM>>>(node_feats, bq, bk, bv, (uint32_t*)pq, (uint32_t*)pk,
                                    (uint32_t*)pv);

    // 2 CTAs per SM
    edge_tc<<<296, 512, EDGE_SMEM>>>(edge_feats, be, bm, src, dst, out + (size_t)NN * 128);

    final_tc<<<148, 256, FIN_SMEM>>>(node_feats, bf1, g_ln, b_ln, out);
}

// round 14
// speedup vs baseline: 1.3456x; 1.0401x over previous
#include <cuda_runtime.h>
#include <cuda_fp16.h>
#include <cstdint>
#include <math.h>

#define NN 50000
#define NE 800000

// fp16 fragment-major strides (32-bit words)
#define ABLK 132  // A block (16r x 16k): 32 lanes x 4 words, pad 128->132
#define BBLK 66   // B block padded (edge kernel)
#define PIT 132   // tf32 pitch for final_tc

// ----------------------------- scratch globals -----------------------------
__device__ uint32_t g_qh[NN * 64];  // q rows, fp16 half2 words
__device__ uint32_t g_kh[NN * 64];
__device__ uint32_t g_vh[NN * 64];
__device__ float g_den[NN * 128];
__device__ float g_h[NN * 128];

__device__ uint32_t g_WhQKV[384 * 128];  // packed [Wq|Wk|Wv], fp16 frag-major
__device__ uint32_t g_WhEM[256 * 128];   // channel-permuted [We|Wm], fp16 frag-major
__device__ uint32_t g_WtF1[128 * 128];   // tf32 [n][k] for final_tc
__device__ uint32_t g_WtF2g[128 * 128];
__device__ float g_vb[128];
__device__ float g_vg[128];

// ----------------------------- helpers -------------------------------------
__device__ __forceinline__ uint32_t rna(float x) {
    uint32_t r;
    asm("cvt.rna.tf32.f32 %0, %1;" : "=r"(r) : "f"(x));
    return r;
}
__device__ __forceinline__ uint32_t pk2(float a, float b) {
    __half2 h = __floats2half2_rn(a, b);
    return *reinterpret_cast<uint32_t*>(&h);
}
__device__ __forceinline__ void mma16(float* c, const uint32_t* a, const uint32_t* b) {
    asm volatile(
        "mma.sync.aligned.m16n8k16.row.col.f32.f16.f16.f32 "
        "{%0,%1,%2,%3}, {%4,%5,%6,%7}, {%8,%9}, {%0,%1,%2,%3};"
        : "+f"(c[0]), "+f"(c[1]), "+f"(c[2]), "+f"(c[3])
        : "r"(a[0]), "r"(a[1]), "r"(a[2]), "r"(a[3]), "r"(b[0]), "r"(b[1]));
}
__device__ __forceinline__ void mma8(float* c, const uint32_t* a, const uint32_t* b) {
    asm volatile(
        "mma.sync.aligned.m16n8k8.row.col.f32.tf32.tf32.f32 "
        "{%0,%1,%2,%3}, {%4,%5,%6,%7}, {%8,%9}, {%0,%1,%2,%3};"
        : "+f"(c[0]), "+f"(c[1]), "+f"(c[2]), "+f"(c[3])
        : "r"(a[0]), "r"(a[1]), "r"(a[2]), "r"(a[3]), "r"(b[0]), "r"(b[1]));
}
__device__ __forceinline__ float mishf(float x) {
    float sp = (x > 20.f) ? x : log1pf(__expf(x));
    return x * tanhf(sp);
}

// fp16 frag-major gmem word index for B value pair (n, k2), k2 = k>>1
__device__ __forceinline__ int fidx16(int n, int k2) {
    return (((n >> 3) << 3) + (k2 >> 3)) * 64 + (((((n & 7) << 2) | (k2 & 3))) << 1) +
           ((k2 >> 2) & 1);
}
// fp16 frag-major smem word index for A halves (r, c), c multiple of 4
__device__ __forceinline__ int aidx16(int r, int c) {
    return ABLK * (((r >> 4) << 3) + (c >> 4)) + ((((r & 7) << 2) | ((c >> 1) & 3)) << 2) +
           ((r >> 3) & 1) + (((c >> 3) & 1) << 1);
}

// ----------------------------- prep kernels --------------------------------
__global__ void prep_T(const float* __restrict__ Wq, const float* __restrict__ Wk,
                       const float* __restrict__ Wv, const float* __restrict__ We,
                       const float* __restrict__ Wm, const float* __restrict__ Wf1,
                       const float* __restrict__ Wf2, const float* __restrict__ gf) {
    int k2 = blockIdx.x, n = threadIdx.x;
    int k0 = k2 * 2, k1 = k0 + 1;
    g_WhQKV[fidx16(n, k2)] = pk2(Wq[k0 * 128 + n], Wq[k1 * 128 + n]);
    g_WhQKV[fidx16(128 + n, k2)] = pk2(Wk[k0 * 128 + n], Wk[k1 * 128 + n]);
    g_WhQKV[fidx16(256 + n, k2)] = pk2(Wv[k0 * 128 + n], Wv[k1 * 128 + n]);
    g_WtF1[n * 128 + k0] = rna(Wf1[k0 * 128 + n]);
    g_WtF1[n * 128 + k1] = rna(Wf1[k1 * 128 + n]);
    g_WtF2g[n * 128 + k0] = rna(gf[k0] * Wf2[k0 * 128 + n]);
    g_WtF2g[n * 128 + k1] = rna(gf[k1] * Wf2[k1 * 128 + n]);
    // EM permutation: GEMM col j -> channel. Thread (wn,t) owns quads
    // cA = wn*32 + t*4 (nt 0..3) and cB = cA+16 (nt 4..7) -> coalesced REDs.
#pragma unroll
    for (int jj = 0; jj < 2; jj++) {
        int j = n + jj * 128;
        int wn = j >> 6, wi = j & 63, nt = wi >> 3, rem = wi & 7, tt = rem >> 1, par = rem & 1;
        int ch = wn * 32 + ((nt >> 2) << 4) + tt * 4 + (nt & 3);
        const float* W = par ? Wm : We;
        g_WhEM[fidx16(j, k2)] = pk2(W[k0 * 128 + ch], W[k1 * 128 + ch]);
    }
}

__global__ void prep_V(const float* __restrict__ Wf2, const float* __restrict__ bf,
                       const float* __restrict__ gf, const float* __restrict__ bf2) {
    int n = threadIdx.x;
    float a = 0.f, b = 0.f;
    for (int k = 0; k < 128; k++) {
        float w = Wf2[k * 128 + n];
        a = fmaf(bf[k], w, a);
        b = fmaf(gf[k], w, b);
    }
    g_vb[n] = bf2[n] + a;
    g_vg[n] = b;
}

// ----------------------------- fused QKV linear -----------------------------
// 512 threads, 64-row tiles, 2 CTAs/SM. q/k/v stored fp16.
// B unpadded (uint2 LDS stride-2 is phase-split conflict-free).
__global__ __launch_bounds__(512) void qkv_tc(
    const float* __restrict__ X,
    const float* __restrict__ bq, const float* __restrict__ bk,
    const float* __restrict__ bv,
    uint32_t* __restrict__ Yq, uint32_t* __restrict__ Yk, uint32_t* __restrict__ Yv) {
    extern __shared__ __align__(16) uint32_t sm[];
    uint32_t* sA = sm;              // 32 blocks * ABLK = 4224 words
    uint32_t* sB = sm + 32 * ABLK;  // 384 blocks * 64 = 24576 words

    int tid = threadIdx.x, w = tid >> 5, lane = tid & 31;
    int wm = w >> 2, wn = w & 3, g = lane >> 2, t = lane & 3;

    for (int i = tid * 4; i < 384 * 64; i += 512 * 4)
        *(uint4*)(sB + i) = *(const uint4*)(g_WhQKV + i);

    int rr = tid >> 3, c8 = (tid & 7) * 4;
    const int M = NN;
    const int nT = (M + 63) >> 6;  // 782
    for (int tt = blockIdx.x; tt < nT; tt += gridDim.x) {
        int base = tt << 6;
        int rowl = min(base + rr, M - 1);
        float4 x0 = __ldg((const float4*)(X + (size_t)rowl * 128 + c8));
        float4 x1 = __ldg((const float4*)(X + (size_t)rowl * 128 + c8 + 32));
        float4 x2 = __ldg((const float4*)(X + (size_t)rowl * 128 + c8 + 64));
        float4 x3 = __ldg((const float4*)(X + (size_t)rowl * 128 + c8 + 96));
        __syncthreads();  // prior tile's MMA reads of sA done
        {
            float4 xs[4] = {x0, x1, x2, x3};
#pragma unroll
            for (int ii = 0; ii < 4; ii++) {
                int c = c8 + ii * 32;
                int w0 = aidx16(rr, c);
                sA[w0] = pk2(xs[ii].x, xs[ii].y);
                sA[w0 + 4] = pk2(xs[ii].z, xs[ii].w);
            }
        }
        __syncthreads();  // sA ready

        int row = base + wm * 16 + g;
#pragma unroll
        for (int sel = 0; sel < 3; sel++) {
            uint32_t* Y = sel == 0 ? Yq : sel == 1 ? Yk : Yv;
            const float* bias = sel == 0 ? bq : sel == 1 ? bk : bv;
            float c_[4][4];
#pragma unroll
            for (int nt = 0; nt < 4; nt++)
#pragma unroll
                for (int i = 0; i < 4; i++) c_[nt][i] = 0.f;
#pragma unroll
            for (int ks = 0; ks < 8; ks++) {
                uint32_t a[4];
                *(uint4*)a = *(const uint4*)(sA + ABLK * (wm * 8 + ks) + lane * 4);
#pragma unroll
                for (int nt = 0; nt < 4; nt++) {
                    uint32_t b[2];
                    int blk = (sel * 16 + wn * 4 + nt) * 8 + ks;
                    *(uint2*)b = *(const uint2*)(sB + blk * 64 + lane * 2);
                    mma16(c_[nt], a, b);
                }
            }
#pragma unroll
            for (int nt = 0; nt < 4; nt++) {
                int col = wn * 32 + nt * 8 + t * 2;
                float b0 = __ldg(bias + col), b1 = __ldg(bias + col + 1);
                if (row < M)
                    Y[(size_t)row * 64 + (col >> 1)] = pk2(c_[nt][0] + b0, c_[nt][1] + b1);
                if (row + 8 < M)
                    Y[(size_t)(row + 8) * 64 + (col >> 1)] = pk2(c_[nt][2] + b0, c_[nt][3] + b1);
            }
        }
    }
}

// ----------------------------- fused edge pass (R13, unchanged) -------------
__global__ __launch_bounds__(512) void edge_tc(
    const float* __restrict__ EF, const float* __restrict__ be,
    const float* __restrict__ bm, const int* __restrict__ src,
    const int* __restrict__ dst, float* __restrict__ outE) {
    extern __shared__ __align__(16) uint32_t sm[];
    uint32_t* sA = sm;               // 32 blocks * ABLK = 4224 words
    uint32_t* sB = sm + 32 * ABLK;   // 256 blocks * BBLK = 16896 words
    float* sbe = (float*)(sB + 256 * BBLK);
    float* sbm = sbe + 128;

    int tid = threadIdx.x, w = tid >> 5, lane = tid & 31;
    int wm = w >> 2, wn = w & 3, g = lane >> 2, t = lane & 3;
    int cA = wn * 32 + t * 4;
    int cB = cA + 16;
    int cAw = cA >> 1, cBw = cB >> 1;

    for (int i = tid; i < 256 * 32; i += 512) {
        int blk = i >> 5, l = i & 31;
        *(uint2*)(sB + blk * BBLK + l * 2) = *(const uint2*)(g_WhEM + blk * 64 + l * 2);
    }
    if (tid < 128) {
        sbe[tid] = be[tid];
        sbm[tid] = bm[tid];
    }

    int rr = tid >> 3;
    int c8 = (tid & 7) * 4;
    int rl0 = wm * 16 + g, rl1 = rl0 + 8;

    const int nT = NE / 64;  // 12500 exact
    for (int tt = blockIdx.x; tt < nT; tt += gridDim.x) {
        int base = tt << 6;
        int s0 = __ldg(src + base + rl0), d0 = __ldg(dst + base + rl0);
        int s1 = __ldg(src + base + rl1), d1 = __ldg(dst + base + rl1);
        float4 x0 = __ldcs((const float4*)(EF + (size_t)(base + rr) * 128 + c8));
        float4 x1 = __ldcs((const float4*)(EF + (size_t)(base + rr) * 128 + c8 + 32));
        float4 x2 = __ldcs((const float4*)(EF + (size_t)(base + rr) * 128 + c8 + 64));
        float4 x3 = __ldcs((const float4*)(EF + (size_t)(base + rr) * 128 + c8 + 96));
        __syncthreads();
        {
            float4 xs[4] = {x0, x1, x2, x3};
#pragma unroll
            for (int ii = 0; ii < 4; ii++) {
                int c = c8 + ii * 32;
                __stcs((float4*)(outE + (size_t)(base + rr) * 128 + c), xs[ii]);
                int w0 = aidx16(rr, c);
                sA[w0] = pk2(xs[ii].x, xs[ii].y);
                sA[w0 + 4] = pk2(xs[ii].z, xs[ii].w);
            }
        }
        __syncthreads();

        float c_[8][4];
#pragma unroll
        for (int nt = 0; nt < 8; nt++)
#pragma unroll
            for (int i = 0; i < 4; i++) c_[nt][i] = 0.f;
#pragma unroll
        for (int ks = 0; ks < 8; ks++) {
            uint32_t a[4];
            *(uint4*)a = *(const uint4*)(sA + ABLK * (wm * 8 + ks) + lane * 4);
#pragma unroll
            for (int nt = 0; nt < 8; nt++) {
                uint32_t b[2];
                *(uint2*)b = *(const uint2*)(sB + BBLK * ((wn * 8 + nt) * 8 + ks) + lane * 2);
                mma16(c_[nt], a, b);
            }
        }

#pragma unroll
        for (int rs = 0; rs < 2; rs++) {
            int s = rs ? s1 : s0, d = rs ? d1 : d0;
            uint2 qA = __ldg((const uint2*)(g_qh + (size_t)s * 64 + cAw));
            uint2 qB = __ldg((const uint2*)(g_qh + (size_t)s * 64 + cBw));
            uint2 kA = __ldg((const uint2*)(g_kh + (size_t)d * 64 + cAw));
            uint2 kB = __ldg((const uint2*)(g_kh + (size_t)d * 64 + cBw));
            uint2 vA = __ldg((const uint2*)(g_vh + (size_t)s * 64 + cAw));
            uint2 vB = __ldg((const uint2*)(g_vh + (size_t)s * 64 + cBw));
            float qa[8], ka[8], va[8];
            {
                float2 f;
                f = __half22float2(*(const __half2*)&qA.x); qa[0] = f.x; qa[1] = f.y;
                f = __half22float2(*(const __half2*)&qA.y); qa[2] = f.x; qa[3] = f.y;
                f = __half22float2(*(const __half2*)&qB.x); qa[4] = f.x; qa[5] = f.y;
                f = __half22float2(*(const __half2*)&qB.y); qa[6] = f.x; qa[7] = f.y;
                f = __half22float2(*(const __half2*)&kA.x); ka[0] = f.x; ka[1] = f.y;
                f = __half22float2(*(const __half2*)&kA.y); ka[2] = f.x; ka[3] = f.y;
                f = __half22float2(*(const __half2*)&kB.x); ka[4] = f.x; ka[5] = f.y;
                f = __half22float2(*(const __half2*)&kB.y); ka[6] = f.x; ka[7] = f.y;
                f = __half22float2(*(const __half2*)&vA.x); va[0] = f.x; va[1] = f.y;
                f = __half22float2(*(const __half2*)&vA.y); va[2] = f.x; va[3] = f.y;
                f = __half22float2(*(const __half2*)&vB.x); va[4] = f.x; va[5] = f.y;
                f = __half22float2(*(const __half2*)&vB.y); va[6] = f.x; va[7] = f.y;
            }
            float p[8], pv[8];
#pragma unroll
            for (int nt = 0; nt < 8; nt++) {
                int ch = (nt < 4) ? (cA + nt) : (cB + nt - 4);
                float ev = c_[nt][rs * 2] + sbe[ch];
                float mv = c_[nt][rs * 2 + 1] + sbm[ch];
                p[nt] = __expf(fmaf(mv, qa[nt] - ka[nt], ev));
                pv[nt] = p[nt] * va[nt];
            }
            float* drow = g_den + (size_t)d * 128;
            float* hrow = g_h + (size_t)d * 128;
            atomicAdd((float4*)(drow + cA), make_float4(p[0], p[1], p[2], p[3]));
            atomicAdd((float4*)(drow + cB), make_float4(p[4], p[5], p[6], p[7]));
            atomicAdd((float4*)(hrow + cA), make_float4(pv[0], pv[1], pv[2], pv[3]));
            atomicAdd((float4*)(hrow + cB), make_float4(pv[4], pv[5], pv[6], pv[7]));
        }
    }
}

// ----------------------------- final fused MLP (512 threads) ----------------
// x = h/den + NF ; u = mish(x@Wf1+bf1) ; LN1 folded through GEMM2 ; LN2.
// 16 warps = 4m x 4n, warp tile m32 x n32 (mt 0..1).
__global__ __launch_bounds__(512, 1) void final_tc(
    const float* __restrict__ NF, const float* __restrict__ bf1,
    const float* __restrict__ gln, const float* __restrict__ bln,
    float* __restrict__ out) {
    extern __shared__ __align__(16) uint32_t sm[];
    uint32_t* sA = sm;
    uint32_t* sB1 = sm + 128 * PIT;
    uint32_t* sB2 = sm + 2 * 128 * PIT;
    float* smu = (float*)(sm + 3 * 128 * PIT);
    float* sinv = smu + 128;
    float* sgl = sinv + 128;
    float* sbl = sgl + 128;

    int tid = threadIdx.x, w = tid >> 5, lane = tid & 31;
    int wm = w >> 2, wn = w & 3, g = lane >> 2, t = lane & 3;

    for (int i = tid; i < 128 * 32; i += 512) {
        int r = i >> 5, c = (i & 31) * 4;
        *(uint4*)(sB1 + r * PIT + c) = *(const uint4*)(g_WtF1 + r * 128 + c);
        *(uint4*)(sB2 + r * PIT + c) = *(const uint4*)(g_WtF2g + r * 128 + c);
    }
    if (tid < 128) {
        sgl[tid] = gln[tid];
        sbl[tid] = bln[tid];
    }
    float b1c[4][2], vbc[4][2], vgc[4][2];
#pragma unroll
    for (int nt = 0; nt < 4; nt++) {
        int col = wn * 32 + nt * 8 + t * 2;
        b1c[nt][0] = __ldg(bf1 + col);   b1c[nt][1] = __ldg(bf1 + col + 1);
        vbc[nt][0] = g_vb[col];          vbc[nt][1] = g_vb[col + 1];
        vgc[nt][0] = g_vg[col];          vgc[nt][1] = g_vg[col + 1];
    }

    int srow = tid >> 2, squad = tid & 3;  // 4 threads per row, 32 cols each
    const int nT = (NN + 127) >> 7;
    for (int tt = blockIdx.x; tt < nT; tt += gridDim.x) {
        __syncthreads();
        int base = tt << 7;
        for (int i = tid; i < 128 * 32; i += 512) {
            int r = i >> 5, c = (i & 31) * 4;
            int row = base + r;
            uint4 u = make_uint4(0u, 0u, 0u, 0u);
            if (row < NN) {
                float4 hh = *(const float4*)(g_h + (size_t)row * 128 + c);
                float4 dn = *(const float4*)(g_den + (size_t)row * 128 + c);
                float4 nf = *(const float4*)(NF + (size_t)row * 128 + c);
                u.x = rna((dn.x > 0.f ? hh.x / dn.x : 0.f) + nf.x);
                u.y = rna((dn.y > 0.f ? hh.y / dn.y : 0.f) + nf.y);
                u.z = rna((dn.z > 0.f ? hh.z / dn.z : 0.f) + nf.z);
                u.w = rna((dn.w > 0.f ? hh.w / dn.w : 0.f) + nf.w);
            }
            *(uint4*)(sA + r * PIT + c) = u;
        }
        __syncthreads();

        // GEMM1: u = x @ Wf1  (warp tile m32 n32)
        float c_[2][4][4];
#pragma unroll
        for (int mt = 0; mt < 2; mt++)
#pragma unroll
            for (int nt = 0; nt < 4; nt++)
#pragma unroll
                for (int i = 0; i < 4; i++) c_[mt][nt][i] = 0.f;
#pragma unroll
        for (int k0 = 0; k0 < 128; k0 += 8) {
            uint32_t a[2][4], b[4][2];
#pragma unroll
            for (int mt = 0; mt < 2; mt++) {
                int r = wm * 32 + mt * 16 + g;
                a[mt][0] = sA[r * PIT + k0 + t];
                a[mt][1] = sA[(r + 8) * PIT + k0 + t];
                a[mt][2] = sA[r * PIT + k0 + t + 4];
                a[mt][3] = sA[(r + 8) * PIT + k0 + t + 4];
            }
#pragma unroll
            for (int nt = 0; nt < 4; nt++) {
                int n = wn * 32 + nt * 8 + g;
                b[nt][0] = sB1[n * PIT + k0 + t];
                b[nt][1] = sB1[n * PIT + k0 + t + 4];
            }
#pragma unroll
            for (int mt = 0; mt < 2; mt++)
#pragma unroll
                for (int nt = 0; nt < 4; nt++) mma8(c_[mt][nt], a[mt], b[nt]);
        }
        __syncthreads();  // all reads of sA(x) done

        // mish, write u (tf32) back to sA
#pragma unroll
        for (int mt = 0; mt < 2; mt++) {
            int r0 = wm * 32 + mt * 16 + g;
#pragma unroll
            for (int nt = 0; nt < 4; nt++) {
                int col = wn * 32 + nt * 8 + t * 2;
                uint2 u0, u1;
                u0.x = rna(mishf(c_[mt][nt][0] + b1c[nt][0]));
                u0.y = rna(mishf(c_[mt][nt][1] + b1c[nt][1]));
                u1.x = rna(mishf(c_[mt][nt][2] + b1c[nt][0]));
                u1.y = rna(mishf(c_[mt][nt][3] + b1c[nt][1]));
                *(uint2*)(sA + r0 * PIT + col) = u0;
                *(uint2*)(sA + (r0 + 8) * PIT + col) = u1;
            }
        }
        __syncthreads();

        // LN1 row stats (4 threads per row)
        {
            float s1 = 0.f, s2 = 0.f;
            const uint32_t* rp = sA + srow * PIT + squad * 32;
#pragma unroll
            for (int i = 0; i < 8; i++) {
                uint4 uu = *(const uint4*)(rp + i * 4);
                float x0 = __uint_as_float(uu.x), x1 = __uint_as_float(uu.y);
                float x2 = __uint_as_float(uu.z), x3 = __uint_as_float(uu.w);
                s1 += x0 + x1 + x2 + x3;
                s2 += x0 * x0 + x1 * x1 + x2 * x2 + x3 * x3;
            }
            s1 += __shfl_xor_sync(0xffffffffu, s1, 1);
            s2 += __shfl_xor_sync(0xffffffffu, s2, 1);
            s1 += __shfl_xor_sync(0xffffffffu, s1, 2);
            s2 += __shfl_xor_sync(0xffffffffu, s2, 2);
            if (squad == 0) {
                float mu = s1 * (1.f / 128.f);
                smu[srow] = mu;
                sinv[srow] = rsqrtf(s2 * (1.f / 128.f) - mu * mu + 1e-5f);
            }
        }
        __syncthreads();

        // GEMM2: acc = u @ (g_f .* Wf2)
        float c2[2][4][4];
#pragma unroll
        for (int mt = 0; mt < 2; mt++)
#pragma unroll
            for (int nt = 0; nt < 4; nt++)
#pragma unroll
                for (int i = 0; i < 4; i++) c2[mt][nt][i] = 0.f;
#pragma unroll
        for (int k0 = 0; k0 < 128; k0 += 8) {
            uint32_t a[2][4], b[4][2];
#pragma unroll
            for (int mt = 0; mt < 2; mt++) {
                int r = wm * 32 + mt * 16 + g;
                a[mt][0] = sA[r * PIT + k0 + t];
                a[mt][1] = sA[(r + 8) * PIT + k0 + t];
                a[mt][2] = sA[r * PIT + k0 + t + 4];
                a[mt][3] = sA[(r + 8) * PIT + k0 + t + 4];
            }
#pragma unroll
            for (int nt = 0; nt < 4; nt++) {
                int n = wn * 32 + nt * 8 + g;
                b[nt][0] = sB2[n * PIT + k0 + t];
                b[nt][1] = sB2[n * PIT + k0 + t + 4];
            }
#pragma unroll
            for (int mt = 0; mt < 2; mt++)
#pragma unroll
                for (int nt = 0; nt < 4; nt++) mma8(c2[mt][nt], a[mt], b[nt]);
        }
        __syncthreads();  // all reads of sA(u) done

        // y = inv1*acc + vb - mu1*inv1*vg, write y (f32 bits) to sA
#pragma unroll
        for (int mt = 0; mt < 2; mt++) {
            int r0 = wm * 32 + mt * 16 + g;
            float mu0 = smu[r0], iv0 = sinv[r0];
            float mu8 = smu[r0 + 8], iv8 = sinv[r0 + 8];
#pragma unroll
            for (int nt = 0; nt < 4; nt++) {
                int col = wn * 32 + nt * 8 + t * 2;
                uint2 y0, y1;
                y0.x = __float_as_uint(iv0 * c2[mt][nt][0] + vbc[nt][0] - mu0 * iv0 * vgc[nt][0]);
                y0.y = __float_as_uint(iv0 * c2[mt][nt][1] + vbc[nt][1] - mu0 * iv0 * vgc[nt][1]);
                y1.x = __float_as_uint(iv8 * c2[mt][nt][2] + vbc[nt][0] - mu8 * iv8 * vgc[nt][0]);
                y1.y = __float_as_uint(iv8 * c2[mt][nt][3] + vbc[nt][1] - mu8 * iv8 * vgc[nt][1]);
                *(uint2*)(sA + r0 * PIT + col) = y0;
                *(uint2*)(sA + (r0 + 8) * PIT + col) = y1;
            }
        }
        __syncthreads();

        // LN2 row stats
        {
            float s1 = 0.f, s2 = 0.f;
            const uint32_t* rp = sA + srow * PIT + squad * 32;
#pragma unroll
            for (int i = 0; i < 8; i++) {
                uint4 uu = *(const uint4*)(rp + i * 4);
                float x0 = __uint_as_float(uu.x), x1 = __uint_as_float(uu.y);
                float x2 = __uint_as_float(uu.z), x3 = __uint_as_float(uu.w);
                s1 += x0 + x1 + x2 + x3;
                s2 += x0 * x0 + x1 * x1 + x2 * x2 + x3 * x3;
            }
            s1 += __shfl_xor_sync(0xffffffffu, s1, 1);
            s2 += __shfl_xor_sync(0xffffffffu, s2, 1);
            s1 += __shfl_xor_sync(0xffffffffu, s1, 2);
            s2 += __shfl_xor_sync(0xffffffffu, s2, 2);
            if (squad == 0) {
                float mu = s1 * (1.f / 128.f);
                smu[srow] = mu;
                sinv[srow] = rsqrtf(s2 * (1.f / 128.f) - mu * mu + 1e-5f);
            }
        }
        __syncthreads();

        // final store
        {
            int row = base + srow;
            if (row < NN) {
                float mu = smu[srow], iv = sinv[srow];
                const uint32_t* rp = sA + srow * PIT + squad * 32;
#pragma unroll
                for (int i = 0; i < 8; i++) {
                    int col = squad * 32 + i * 4;
                    uint4 uu = *(const uint4*)(rp + i * 4);
                    float4 o;
                    o.x = (__uint_as_float(uu.x) - mu) * iv * sgl[col + 0] + sbl[col + 0];
                    o.y = (__uint_as_float(uu.y) - mu) * iv * sgl[col + 1] + sbl[col + 1];
                    o.z = (__uint_as_float(uu.z) - mu) * iv * sgl[col + 2] + sbl[col + 2];
                    o.w = (__uint_as_float(uu.w) - mu) * iv * sgl[col + 3] + sbl[col + 3];
                    *(float4*)(out + (size_t)row * 128 + col) = o;
                }
            }
        }
    }
}

// ---------------------------------------------------------------------------
extern "C" void kernel_launch(void* const* d_in, const int* in_sizes, int n_in,
                              void* d_out, int out_size) {
    const float* node_feats = (const float*)d_in[0];
    const float* edge_feats = (const float*)d_in[1];
    const int* src = (const int*)d_in[2];
    const int* dst = (const int*)d_in[3];
    const float* Wq = (const float*)d_in[4];
    const float* bq = (const float*)d_in[5];
    const float* Wk = (const float*)d_in[6];
    const float* bk = (const float*)d_in[7];
    const float* Wv = (const float*)d_in[8];
    const float* bv = (const float*)d_in[9];
    const float* We = (const float*)d_in[10];
    const float* be = (const float*)d_in[11];
    const float* Wm = (const float*)d_in[12];
    const float* bm = (const float*)d_in[13];
    const float* Wf1 = (const float*)d_in[14];
    const float* bf1 = (const float*)d_in[15];
    const float* g_f = (const float*)d_in[16];
    const float* b_f = (const float*)d_in[17];
    const float* Wf2 = (const float*)d_in[18];
    const float* bf2 = (const float*)d_in[19];
    const float* g_ln = (const float*)d_in[20];
    const float* b_ln = (const float*)d_in[21];
    float* out = (float*)d_out;

    void *pden, *ph, *pq, *pk, *pv;
    cudaGetSymbolAddress(&pden, g_den);
    cudaGetSymbolAddress(&ph, g_h);
    cudaGetSymbolAddress(&pq, g_qh);
    cudaGetSymbolAddress(&pk, g_kh);
    cudaGetSymbolAddress(&pv, g_vh);

    const size_t QKV_SMEM = (size_t)(32 * ABLK + 384 * 64) * 4;           // 115200 (2 CTAs/SM)
    const size_t EDGE_SMEM = (size_t)(32 * ABLK + 256 * BBLK + 256) * 4;  // 85504 (2 CTAs/SM)
    const size_t FIN_SMEM = (size_t)(3 * 128 * PIT + 512) * 4;            // 204800
    cudaFuncSetAttribute(qkv_tc, cudaFuncAttributeMaxDynamicSharedMemorySize, (int)QKV_SMEM);
    cudaFuncSetAttribute(edge_tc, cudaFuncAttributeMaxDynamicSharedMemorySize, (int)EDGE_SMEM);
    cudaFuncSetAttribute(final_tc, cudaFuncAttributeMaxDynamicSharedMemorySize, (int)FIN_SMEM);

    cudaMemsetAsync(pden, 0, (size_t)NN * 128 * sizeof(float), 0);
    cudaMemsetAsync(ph, 0, (size_t)NN * 128 * sizeof(float), 0);

    prep_T<<<64, 128>>>(Wq, Wk, Wv, We, Wm, Wf1, Wf2, g_f);
    prep_V<<<1, 128>>>(Wf2, b_f, g_f, bf2);

    qkv_tc<<<296, 512, QKV_SMEM>>>(node_feats, bq, bk, bv, (uint32_t*)pq, (uint32_t*)pk,
                                   (uint32_t*)pv);

    edge_tc<<<296, 512, EDGE_SMEM>>>(edge_feats, be, bm, src, dst, out + (size_t)NN * 128);

    final_tc<<<148, 512, FIN_SMEM>>>(node_feats, bf1, g_ln, b_ln, out);
}

// round 15
// speedup vs baseline: 1.3474x; 1.0013x over previous
#include <cuda_runtime.h>
#include <cuda_fp16.h>
#include <cstdint>
#include <math.h>

#define NN 50000
#define NE 800000

// fp16 fragment-major strides (32-bit words)
#define ABLK 132  // A block (16r x 16k): 32 lanes x 4 words, pad 128->132
#define BBLK 66   // B block padded (edge kernel)

// ----------------------------- scratch globals -----------------------------
__device__ uint32_t g_qh[NN * 64];  // q rows, fp16 half2 words
__device__ uint32_t g_kh[NN * 64];
__device__ uint32_t g_vh[NN * 64];
__device__ float g_den[NN * 128];
__device__ float g_h[NN * 128];

__device__ uint32_t g_WhQKV[384 * 128];  // packed [Wq|Wk|Wv], fp16 frag-major
__device__ uint32_t g_WhEM[256 * 128];   // channel-permuted [We|Wm], fp16 frag-major
__device__ uint32_t g_WhF1[128 * 64];    // Wf1 fp16 frag-major
__device__ uint32_t g_WhF2g[128 * 64];   // g_f .* Wf2 fp16 frag-major
__device__ float g_vb[128];
__device__ float g_vg[128];

// ----------------------------- helpers -------------------------------------
__device__ __forceinline__ uint32_t pk2(float a, float b) {
    __half2 h = __floats2half2_rn(a, b);
    return *reinterpret_cast<uint32_t*>(&h);
}
__device__ __forceinline__ void mma16(float* c, const uint32_t* a, const uint32_t* b) {
    asm volatile(
        "mma.sync.aligned.m16n8k16.row.col.f32.f16.f16.f32 "
        "{%0,%1,%2,%3}, {%4,%5,%6,%7}, {%8,%9}, {%0,%1,%2,%3};"
        : "+f"(c[0]), "+f"(c[1]), "+f"(c[2]), "+f"(c[3])
        : "r"(a[0]), "r"(a[1]), "r"(a[2]), "r"(a[3]), "r"(b[0]), "r"(b[1]));
}
__device__ __forceinline__ float mishf(float x) {
    float sp = (x > 20.f) ? x : log1pf(__expf(x));
    return x * tanhf(sp);
}

// fp16 frag-major gmem word index for B value pair (n, k2), k2 = k>>1
__device__ __forceinline__ int fidx16(int n, int k2) {
    return (((n >> 3) << 3) + (k2 >> 3)) * 64 + (((((n & 7) << 2) | (k2 & 3))) << 1) +
           ((k2 >> 2) & 1);
}
// fp16 frag-major smem word index for A halves (r, c), c even
__device__ __forceinline__ int aidx16(int r, int c) {
    return ABLK * (((r >> 4) << 3) + (c >> 4)) + ((((r & 7) << 2) | ((c >> 1) & 3)) << 2) +
           ((r >> 3) & 1) + (((c >> 3) & 1) << 1);
}

// ----------------------------- prep kernels --------------------------------
__global__ void prep_T(const float* __restrict__ Wq, const float* __restrict__ Wk,
                       const float* __restrict__ Wv, const float* __restrict__ We,
                       const float* __restrict__ Wm, const float* __restrict__ Wf1,
                       const float* __restrict__ Wf2, const float* __restrict__ gf) {
    int k2 = blockIdx.x, n = threadIdx.x;
    int k0 = k2 * 2, k1 = k0 + 1;
    g_WhQKV[fidx16(n, k2)] = pk2(Wq[k0 * 128 + n], Wq[k1 * 128 + n]);
    g_WhQKV[fidx16(128 + n, k2)] = pk2(Wk[k0 * 128 + n], Wk[k1 * 128 + n]);
    g_WhQKV[fidx16(256 + n, k2)] = pk2(Wv[k0 * 128 + n], Wv[k1 * 128 + n]);
    g_WhF1[fidx16(n, k2)] = pk2(Wf1[k0 * 128 + n], Wf1[k1 * 128 + n]);
    g_WhF2g[fidx16(n, k2)] = pk2(gf[k0] * Wf2[k0 * 128 + n], gf[k1] * Wf2[k1 * 128 + n]);
    // EM permutation: GEMM col j -> channel. Thread (wn,t) owns quads
    // cA = wn*32 + t*4 (nt 0..3) and cB = cA+16 (nt 4..7) -> coalesced REDs.
#pragma unroll
    for (int jj = 0; jj < 2; jj++) {
        int j = n + jj * 128;
        int wn = j >> 6, wi = j & 63, nt = wi >> 3, rem = wi & 7, tt = rem >> 1, par = rem & 1;
        int ch = wn * 32 + ((nt >> 2) << 4) + tt * 4 + (nt & 3);
        const float* W = par ? Wm : We;
        g_WhEM[fidx16(j, k2)] = pk2(W[k0 * 128 + ch], W[k1 * 128 + ch]);
    }
}

__global__ void prep_V(const float* __restrict__ Wf2, const float* __restrict__ bf,
                       const float* __restrict__ gf, const float* __restrict__ bf2) {
    int n = threadIdx.x;
    float a = 0.f, b = 0.f;
    for (int k = 0; k < 128; k++) {
        float w = Wf2[k * 128 + n];
        a = fmaf(bf[k], w, a);
        b = fmaf(gf[k], w, b);
    }
    g_vb[n] = bf2[n] + a;
    g_vg[n] = b;
}

// ----------------------------- fused QKV linear (R14, unchanged) ------------
__global__ __launch_bounds__(512) void qkv_tc(
    const float* __restrict__ X,
    const float* __restrict__ bq, const float* __restrict__ bk,
    const float* __restrict__ bv,
    uint32_t* __restrict__ Yq, uint32_t* __restrict__ Yk, uint32_t* __restrict__ Yv) {
    extern __shared__ __align__(16) uint32_t sm[];
    uint32_t* sA = sm;              // 32 blocks * ABLK = 4224 words
    uint32_t* sB = sm + 32 * ABLK;  // 384 blocks * 64 = 24576 words

    int tid = threadIdx.x, w = tid >> 5, lane = tid & 31;
    int wm = w >> 2, wn = w & 3, g = lane >> 2, t = lane & 3;

    for (int i = tid * 4; i < 384 * 64; i += 512 * 4)
        *(uint4*)(sB + i) = *(const uint4*)(g_WhQKV + i);

    int rr = tid >> 3, c8 = (tid & 7) * 4;
    const int M = NN;
    const int nT = (M + 63) >> 6;  // 782
    for (int tt = blockIdx.x; tt < nT; tt += gridDim.x) {
        int base = tt << 6;
        int rowl = min(base + rr, M - 1);
        float4 x0 = __ldg((const float4*)(X + (size_t)rowl * 128 + c8));
        float4 x1 = __ldg((const float4*)(X + (size_t)rowl * 128 + c8 + 32));
        float4 x2 = __ldg((const float4*)(X + (size_t)rowl * 128 + c8 + 64));
        float4 x3 = __ldg((const float4*)(X + (size_t)rowl * 128 + c8 + 96));
        __syncthreads();
        {
            float4 xs[4] = {x0, x1, x2, x3};
#pragma unroll
            for (int ii = 0; ii < 4; ii++) {
                int c = c8 + ii * 32;
                int w0 = aidx16(rr, c);
                sA[w0] = pk2(xs[ii].x, xs[ii].y);
                sA[w0 + 4] = pk2(xs[ii].z, xs[ii].w);
            }
        }
        __syncthreads();

        int row = base + wm * 16 + g;
#pragma unroll
        for (int sel = 0; sel < 3; sel++) {
            uint32_t* Y = sel == 0 ? Yq : sel == 1 ? Yk : Yv;
            const float* bias = sel == 0 ? bq : sel == 1 ? bk : bv;
            float c_[4][4];
#pragma unroll
            for (int nt = 0; nt < 4; nt++)
#pragma unroll
                for (int i = 0; i < 4; i++) c_[nt][i] = 0.f;
#pragma unroll
            for (int ks = 0; ks < 8; ks++) {
                uint32_t a[4];
                *(uint4*)a = *(const uint4*)(sA + ABLK * (wm * 8 + ks) + lane * 4);
#pragma unroll
                for (int nt = 0; nt < 4; nt++) {
                    uint32_t b[2];
                    int blk = (sel * 16 + wn * 4 + nt) * 8 + ks;
                    *(uint2*)b = *(const uint2*)(sB + blk * 64 + lane * 2);
                    mma16(c_[nt], a, b);
                }
            }
#pragma unroll
            for (int nt = 0; nt < 4; nt++) {
                int col = wn * 32 + nt * 8 + t * 2;
                float b0 = __ldg(bias + col), b1 = __ldg(bias + col + 1);
                if (row < M)
                    Y[(size_t)row * 64 + (col >> 1)] = pk2(c_[nt][0] + b0, c_[nt][1] + b1);
                if (row + 8 < M)
                    Y[(size_t)(row + 8) * 64 + (col >> 1)] = pk2(c_[nt][2] + b0, c_[nt][3] + b1);
            }
        }
    }
}

// ----------------------------- fused edge pass (R13/R14, unchanged) ---------
__global__ __launch_bounds__(512) void edge_tc(
    const float* __restrict__ EF, const float* __restrict__ be,
    const float* __restrict__ bm, const int* __restrict__ src,
    const int* __restrict__ dst, float* __restrict__ outE) {
    extern __shared__ __align__(16) uint32_t sm[];
    uint32_t* sA = sm;               // 32 blocks * ABLK = 4224 words
    uint32_t* sB = sm + 32 * ABLK;   // 256 blocks * BBLK = 16896 words
    float* sbe = (float*)(sB + 256 * BBLK);
    float* sbm = sbe + 128;

    int tid = threadIdx.x, w = tid >> 5, lane = tid & 31;
    int wm = w >> 2, wn = w & 3, g = lane >> 2, t = lane & 3;
    int cA = wn * 32 + t * 4;
    int cB = cA + 16;
    int cAw = cA >> 1, cBw = cB >> 1;

    for (int i = tid; i < 256 * 32; i += 512) {
        int blk = i >> 5, l = i & 31;
        *(uint2*)(sB + blk * BBLK + l * 2) = *(const uint2*)(g_WhEM + blk * 64 + l * 2);
    }
    if (tid < 128) {
        sbe[tid] = be[tid];
        sbm[tid] = bm[tid];
    }

    int rr = tid >> 3;
    int c8 = (tid & 7) * 4;
    int rl0 = wm * 16 + g, rl1 = rl0 + 8;

    const int nT = NE / 64;  // 12500 exact
    for (int tt = blockIdx.x; tt < nT; tt += gridDim.x) {
        int base = tt << 6;
        int s0 = __ldg(src + base + rl0), d0 = __ldg(dst + base + rl0);
        int s1 = __ldg(src + base + rl1), d1 = __ldg(dst + base + rl1);
        float4 x0 = __ldcs((const float4*)(EF + (size_t)(base + rr) * 128 + c8));
        float4 x1 = __ldcs((const float4*)(EF + (size_t)(base + rr) * 128 + c8 + 32));
        float4 x2 = __ldcs((const float4*)(EF + (size_t)(base + rr) * 128 + c8 + 64));
        float4 x3 = __ldcs((const float4*)(EF + (size_t)(base + rr) * 128 + c8 + 96));
        __syncthreads();
        {
            float4 xs[4] = {x0, x1, x2, x3};
#pragma unroll
            for (int ii = 0; ii < 4; ii++) {
                int c = c8 + ii * 32;
                __stcs((float4*)(outE + (size_t)(base + rr) * 128 + c), xs[ii]);
                int w0 = aidx16(rr, c);
                sA[w0] = pk2(xs[ii].x, xs[ii].y);
                sA[w0 + 4] = pk2(xs[ii].z, xs[ii].w);
            }
        }
        __syncthreads();

        float c_[8][4];
#pragma unroll
        for (int nt = 0; nt < 8; nt++)
#pragma unroll
            for (int i = 0; i < 4; i++) c_[nt][i] = 0.f;
#pragma unroll
        for (int ks = 0; ks < 8; ks++) {
            uint32_t a[4];
            *(uint4*)a = *(const uint4*)(sA + ABLK * (wm * 8 + ks) + lane * 4);
#pragma unroll
            for (int nt = 0; nt < 8; nt++) {
                uint32_t b[2];
                *(uint2*)b = *(const uint2*)(sB + BBLK * ((wn * 8 + nt) * 8 + ks) + lane * 2);
                mma16(c_[nt], a, b);
            }
        }

#pragma unroll
        for (int rs = 0; rs < 2; rs++) {
            int s = rs ? s1 : s0, d = rs ? d1 : d0;
            uint2 qA = __ldg((const uint2*)(g_qh + (size_t)s * 64 + cAw));
            uint2 qB = __ldg((const uint2*)(g_qh + (size_t)s * 64 + cBw));
            uint2 kA = __ldg((const uint2*)(g_kh + (size_t)d * 64 + cAw));
            uint2 kB = __ldg((const uint2*)(g_kh + (size_t)d * 64 + cBw));
            uint2 vA = __ldg((const uint2*)(g_vh + (size_t)s * 64 + cAw));
            uint2 vB = __ldg((const uint2*)(g_vh + (size_t)s * 64 + cBw));
            float qa[8], ka[8], va[8];
            {
                float2 f;
                f = __half22float2(*(const __half2*)&qA.x); qa[0] = f.x; qa[1] = f.y;
                f = __half22float2(*(const __half2*)&qA.y); qa[2] = f.x; qa[3] = f.y;
                f = __half22float2(*(const __half2*)&qB.x); qa[4] = f.x; qa[5] = f.y;
                f = __half22float2(*(const __half2*)&qB.y); qa[6] = f.x; qa[7] = f.y;
                f = __half22float2(*(const __half2*)&kA.x); ka[0] = f.x; ka[1] = f.y;
                f = __half22float2(*(const __half2*)&kA.y); ka[2] = f.x; ka[3] = f.y;
                f = __half22float2(*(const __half2*)&kB.x); ka[4] = f.x; ka[5] = f.y;
                f = __half22float2(*(const __half2*)&kB.y); ka[6] = f.x; ka[7] = f.y;
                f = __half22float2(*(const __half2*)&vA.x); va[0] = f.x; va[1] = f.y;
                f = __half22float2(*(const __half2*)&vA.y); va[2] = f.x; va[3] = f.y;
                f = __half22float2(*(const __half2*)&vB.x); va[4] = f.x; va[5] = f.y;
                f = __half22float2(*(const __half2*)&vB.y); va[6] = f.x; va[7] = f.y;
            }
            float p[8], pv[8];
#pragma unroll
            for (int nt = 0; nt < 8; nt++) {
                int ch = (nt < 4) ? (cA + nt) : (cB + nt - 4);
                float ev = c_[nt][rs * 2] + sbe[ch];
                float mv = c_[nt][rs * 2 + 1] + sbm[ch];
                p[nt] = __expf(fmaf(mv, qa[nt] - ka[nt], ev));
                pv[nt] = p[nt] * va[nt];
            }
            float* drow = g_den + (size_t)d * 128;
            float* hrow = g_h + (size_t)d * 128;
            atomicAdd((float4*)(drow + cA), make_float4(p[0], p[1], p[2], p[3]));
            atomicAdd((float4*)(drow + cB), make_float4(p[4], p[5], p[6], p[7]));
            atomicAdd((float4*)(hrow + cA), make_float4(pv[0], pv[1], pv[2], pv[3]));
            atomicAdd((float4*)(hrow + cB), make_float4(pv[4], pv[5], pv[6], pv[7]));
        }
    }
}

// ----------------------------- final fused MLP (fp16, 2 CTAs/SM) ------------
// x = h/den + NF ; u = mish(x@Wf1+bf1) ; LN1 folded through GEMM2 ;
// out = LN2(y)*g_ln + b_ln. Register-resident LN (shfl + tiny partials).
// 512 thr = 16 warps (4m x 4n), warp tile m32 x n32, fp16 frag-major.
__global__ __launch_bounds__(512, 2) void final_tc(
    const float* __restrict__ NF, const float* __restrict__ bf1,
    const float* __restrict__ gln, const float* __restrict__ bln,
    float* __restrict__ out) {
    extern __shared__ __align__(16) uint32_t sm[];
    uint32_t* sAh = sm;            // 64 blocks * ABLK = 8448 words
    uint32_t* sB1 = sm + 8448;     // 8192
    uint32_t* sB2 = sm + 16640;    // 8192
    float* sP1 = (float*)(sm + 24832);  // 512
    float* sP2 = sP1 + 512;             // 512
    float* smu = sP2 + 512;             // 128
    float* sinv = smu + 128;            // 128

    int tid = threadIdx.x, w = tid >> 5, lane = tid & 31;
    int wm = w >> 2, wn = w & 3, g = lane >> 2, t = lane & 3;

    for (int i = tid * 4; i < 8192; i += 512 * 4) {
        *(uint4*)(sB1 + i) = *(const uint4*)(g_WhF1 + i);
        *(uint4*)(sB2 + i) = *(const uint4*)(g_WhF2g + i);
    }
    float b1c[4][2], vbc[4][2], vgc[4][2], glc[4][2], blc[4][2];
#pragma unroll
    for (int nt = 0; nt < 4; nt++) {
        int col = wn * 32 + nt * 8 + t * 2;
        b1c[nt][0] = __ldg(bf1 + col);  b1c[nt][1] = __ldg(bf1 + col + 1);
        vbc[nt][0] = g_vb[col];         vbc[nt][1] = g_vb[col + 1];
        vgc[nt][0] = g_vg[col];         vgc[nt][1] = g_vg[col + 1];
        glc[nt][0] = __ldg(gln + col);  glc[nt][1] = __ldg(gln + col + 1);
        blc[nt][0] = __ldg(bln + col);  blc[nt][1] = __ldg(bln + col + 1);
    }

    int rr = tid >> 2, c32 = (tid & 3) * 32;  // x-load: 4 threads per row
    const int nT = (NN + 127) >> 7;
    for (int tt = blockIdx.x; tt < nT; tt += gridDim.x) {
        int base = tt << 7;
        __syncthreads();  // prior tile done (stores/partials)
        // 1. x = h/den + NF -> fp16 sAh  (each thread: 1 row, 32 cols)
#pragma unroll
        for (int ii = 0; ii < 8; ii++) {
            int c = c32 + ii * 4;
            int row = min(base + rr, NN - 1);
            float4 hh = *(const float4*)(g_h + (size_t)row * 128 + c);
            float4 dn = *(const float4*)(g_den + (size_t)row * 128 + c);
            float4 nf = __ldg((const float4*)(NF + (size_t)row * 128 + c));
            float x0 = (dn.x > 0.f ? hh.x / dn.x : 0.f) + nf.x;
            float x1 = (dn.y > 0.f ? hh.y / dn.y : 0.f) + nf.y;
            float x2 = (dn.z > 0.f ? hh.z / dn.z : 0.f) + nf.z;
            float x3 = (dn.w > 0.f ? hh.w / dn.w : 0.f) + nf.w;
            int w0 = aidx16(rr, c);
            sAh[w0] = pk2(x0, x1);
            sAh[w0 + 4] = pk2(x2, x3);
        }
        __syncthreads();

        // 2. GEMM1: u_acc = x @ Wf1
        float c_[2][4][4];
#pragma unroll
        for (int mt = 0; mt < 2; mt++)
#pragma unroll
            for (int nt = 0; nt < 4; nt++)
#pragma unroll
                for (int i = 0; i < 4; i++) c_[mt][nt][i] = 0.f;
#pragma unroll
        for (int ks = 0; ks < 8; ks++) {
            uint32_t a[2][4];
#pragma unroll
            for (int mt = 0; mt < 2; mt++)
                *(uint4*)(a[mt]) = *(const uint4*)(sAh + ABLK * ((wm * 2 + mt) * 8 + ks) + lane * 4);
#pragma unroll
            for (int nt = 0; nt < 4; nt++) {
                uint32_t b[2];
                *(uint2*)b = *(const uint2*)(sB1 + ((wn * 4 + nt) * 8 + ks) * 64 + lane * 2);
                mma16(c_[0][nt], a[0], b);
                mma16(c_[1][nt], a[1], b);
            }
        }
        __syncthreads();  // all GEMM1 reads of sAh done

        // 3. mish -> u (write fp16 to sAh), register LN1 partials
        float s1[2][2], s2[2][2];
#pragma unroll
        for (int mt = 0; mt < 2; mt++) {
            s1[mt][0] = s1[mt][1] = s2[mt][0] = s2[mt][1] = 0.f;
            int r0 = wm * 32 + mt * 16 + g;
#pragma unroll
            for (int nt = 0; nt < 4; nt++) {
                int col = wn * 32 + nt * 8 + t * 2;
                float u0 = mishf(c_[mt][nt][0] + b1c[nt][0]);
                float u1 = mishf(c_[mt][nt][1] + b1c[nt][1]);
                float u2 = mishf(c_[mt][nt][2] + b1c[nt][0]);
                float u3 = mishf(c_[mt][nt][3] + b1c[nt][1]);
                sAh[aidx16(r0, col)] = pk2(u0, u1);
                sAh[aidx16(r0 + 8, col)] = pk2(u2, u3);
                s1[mt][0] += u0 + u1; s2[mt][0] += u0 * u0 + u1 * u1;
                s1[mt][1] += u2 + u3; s2[mt][1] += u2 * u2 + u3 * u3;
            }
        }
#pragma unroll
        for (int mt = 0; mt < 2; mt++)
#pragma unroll
            for (int hh = 0; hh < 2; hh++) {
                s1[mt][hh] += __shfl_xor_sync(0xffffffffu, s1[mt][hh], 1);
                s2[mt][hh] += __shfl_xor_sync(0xffffffffu, s2[mt][hh], 1);
                s1[mt][hh] += __shfl_xor_sync(0xffffffffu, s1[mt][hh], 2);
                s2[mt][hh] += __shfl_xor_sync(0xffffffffu, s2[mt][hh], 2);
            }
        if (t == 0) {
#pragma unroll
            for (int mt = 0; mt < 2; mt++)
#pragma unroll
                for (int hh = 0; hh < 2; hh++) {
                    int row = wm * 32 + mt * 16 + g + hh * 8;
                    sP1[row * 4 + wn] = s1[mt][hh];
                    sP2[row * 4 + wn] = s2[mt][hh];
                }
        }
        __syncthreads();

        // 4. reduce LN1 stats
        if (tid < 128) {
            float a1 = sP1[tid * 4] + sP1[tid * 4 + 1] + sP1[tid * 4 + 2] + sP1[tid * 4 + 3];
            float a2 = sP2[tid * 4] + sP2[tid * 4 + 1] + sP2[tid * 4 + 2] + sP2[tid * 4 + 3];
            float mu = a1 * (1.f / 128.f);
            smu[tid] = mu;
            sinv[tid] = rsqrtf(a2 * (1.f / 128.f) - mu * mu + 1e-5f);
        }
        __syncthreads();

        // 5. GEMM2 + affine (y in registers)
        float c2[2][4][4];
#pragma unroll
        for (int mt = 0; mt < 2; mt++)
#pragma unroll
            for (int nt = 0; nt < 4; nt++)
#pragma unroll
                for (int i = 0; i < 4; i++) c2[mt][nt][i] = 0.f;
#pragma unroll
        for (int ks = 0; ks < 8; ks++) {
            uint32_t a[2][4];
#pragma unroll
            for (int mt = 0; mt < 2; mt++)
                *(uint4*)(a[mt]) = *(const uint4*)(sAh + ABLK * ((wm * 2 + mt) * 8 + ks) + lane * 4);
#pragma unroll
            for (int nt = 0; nt < 4; nt++) {
                uint32_t b[2];
                *(uint2*)b = *(const uint2*)(sB2 + ((wn * 4 + nt) * 8 + ks) * 64 + lane * 2);
                mma16(c2[0][nt], a[0], b);
                mma16(c2[1][nt], a[1], b);
            }
        }
#pragma unroll
        for (int mt = 0; mt < 2; mt++) {
            int r0 = wm * 32 + mt * 16 + g;
            float mu0 = smu[r0], iv0 = sinv[r0];
            float mu8 = smu[r0 + 8], iv8 = sinv[r0 + 8];
            s1[mt][0] = s1[mt][1] = s2[mt][0] = s2[mt][1] = 0.f;
#pragma unroll
            for (int nt = 0; nt < 4; nt++) {
                float y0 = iv0 * c2[mt][nt][0] + vbc[nt][0] - mu0 * iv0 * vgc[nt][0];
                float y1 = iv0 * c2[mt][nt][1] + vbc[nt][1] - mu0 * iv0 * vgc[nt][1];
                float y2 = iv8 * c2[mt][nt][2] + vbc[nt][0] - mu8 * iv8 * vgc[nt][0];
                float y3 = iv8 * c2[mt][nt][3] + vbc[nt][1] - mu8 * iv8 * vgc[nt][1];
                c2[mt][nt][0] = y0; c2[mt][nt][1] = y1;
                c2[mt][nt][2] = y2; c2[mt][nt][3] = y3;
                s1[mt][0] += y0 + y1; s2[mt][0] += y0 * y0 + y1 * y1;
                s1[mt][1] += y2 + y3; s2[mt][1] += y2 * y2 + y3 * y3;
            }
        }
        // 6. LN2 partials
#pragma unroll
        for (int mt = 0; mt < 2; mt++)
#pragma unroll
            for (int hh = 0; hh < 2; hh++) {
                s1[mt][hh] += __shfl_xor_sync(0xffffffffu, s1[mt][hh], 1);
                s2[mt][hh] += __shfl_xor_sync(0xffffffffu, s2[mt][hh], 1);
                s1[mt][hh] += __shfl_xor_sync(0xffffffffu, s1[mt][hh], 2);
                s2[mt][hh] += __shfl_xor_sync(0xffffffffu, s2[mt][hh], 2);
            }
        if (t == 0) {
#pragma unroll
            for (int mt = 0; mt < 2; mt++)
#pragma unroll
                for (int hh = 0; hh < 2; hh++) {
                    int row = wm * 32 + mt * 16 + g + hh * 8;
                    sP1[row * 4 + wn] = s1[mt][hh];
                    sP2[row * 4 + wn] = s2[mt][hh];
                }
        }
        __syncthreads();
        if (tid < 128) {
            float a1 = sP1[tid * 4] + sP1[tid * 4 + 1] + sP1[tid * 4 + 2] + sP1[tid * 4 + 3];
            float a2 = sP2[tid * 4] + sP2[tid * 4 + 1] + sP2[tid * 4 + 2] + sP2[tid * 4 + 3];
            float mu = a1 * (1.f / 128.f);
            smu[tid] = mu;
            sinv[tid] = rsqrtf(a2 * (1.f / 128.f) - mu * mu + 1e-5f);
        }
        __syncthreads();

        // 7. normalize + store from registers
#pragma unroll
        for (int mt = 0; mt < 2; mt++) {
            int r0 = wm * 32 + mt * 16 + g;
            float mu0 = smu[r0], iv0 = sinv[r0];
            float mu8 = smu[r0 + 8], iv8 = sinv[r0 + 8];
            int row0 = base + r0, row8 = row0 + 8;
#pragma unroll
            for (int nt = 0; nt < 4; nt++) {
                int col = wn * 32 + nt * 8 + t * 2;
                if (row0 < NN) {
                    float2 o;
                    o.x = (c2[mt][nt][0] - mu0) * iv0 * glc[nt][0] + blc[nt][0];
                    o.y = (c2[mt][nt][1] - mu0) * iv0 * glc[nt][1] + blc[nt][1];
                    *(float2*)(out + (size_t)row0 * 128 + col) = o;
                }
                if (row8 < NN) {
                    float2 o;
                    o.x = (c2[mt][nt][2] - mu8) * iv8 * glc[nt][0] + blc[nt][0];
                    o.y = (c2[mt][nt][3] - mu8) * iv8 * glc[nt][1] + blc[nt][1];
                    *(float2*)(out + (size_t)row8 * 128 + col) = o;
                }
            }
        }
    }
}

// ---------------------------------------------------------------------------
extern "C" void kernel_launch(void* const* d_in, const int* in_sizes, int n_in,
                              void* d_out, int out_size) {
    const float* node_feats = (const float*)d_in[0];
    const float* edge_feats = (const float*)d_in[1];
    const int* src = (const int*)d_in[2];
    const int* dst = (const int*)d_in[3];
    const float* Wq = (const float*)d_in[4];
    const float* bq = (const float*)d_in[5];
    const float* Wk = (const float*)d_in[6];
    const float* bk = (const float*)d_in[7];
    const float* Wv = (const float*)d_in[8];
    const float* bv = (const float*)d_in[9];
    const float* We = (const float*)d_in[10];
    const float* be = (const float*)d_in[11];
    const float* Wm = (const float*)d_in[12];
    const float* bm = (const float*)d_in[13];
    const float* Wf1 = (const float*)d_in[14];
    const float* bf1 = (const float*)d_in[15];
    const float* g_f = (const float*)d_in[16];
    const float* b_f = (const float*)d_in[17];
    const float* Wf2 = (const float*)d_in[18];
    const float* bf2 = (const float*)d_in[19];
    const float* g_ln = (const float*)d_in[20];
    const float* b_ln = (const float*)d_in[21];
    float* out = (float*)d_out;

    void *pden, *ph, *pq, *pk, *pv;
    cudaGetSymbolAddress(&pden, g_den);
    cudaGetSymbolAddress(&ph, g_h);
    cudaGetSymbolAddress(&pq, g_qh);
    cudaGetSymbolAddress(&pk, g_kh);
    cudaGetSymbolAddress(&pv, g_vh);

    const size_t QKV_SMEM = (size_t)(32 * ABLK + 384 * 64) * 4;           // 115200 (2/SM)
    const size_t EDGE_SMEM = (size_t)(32 * ABLK + 256 * BBLK + 256) * 4;  // 85504 (2/SM)
    const size_t FIN_SMEM = (size_t)(8448 + 8192 + 8192 + 512 + 512 + 256) * 4;  // 104448 (2/SM)
    cudaFuncSetAttribute(qkv_tc, cudaFuncAttributeMaxDynamicSharedMemorySize, (int)QKV_SMEM);
    cudaFuncSetAttribute(edge_tc, cudaFuncAttributeMaxDynamicSharedMemorySize, (int)EDGE_SMEM);
    cudaFuncSetAttribute(final_tc, cudaFuncAttributeMaxDynamicSharedMemorySize, (int)FIN_SMEM);

    cudaMemsetAsync(pden, 0, (size_t)NN * 128 * sizeof(float), 0);
    cudaMemsetAsync(ph, 0, (size_t)NN * 128 * sizeof(float), 0);

    prep_T<<<64, 128>>>(Wq, Wk, Wv, We, Wm, Wf1, Wf2, g_f);
    prep_V<<<1, 128>>>(Wf2, b_f, g_f, bf2);

    qkv_tc<<<296, 512, QKV_SMEM>>>(node_feats, bq, bk, bv, (uint32_t*)pq, (uint32_t*)pk,
                                   (uint32_t*)pv);

    edge_tc<<<296, 512, EDGE_SMEM>>>(edge_feats, be, bm, src, dst, out + (size_t)NN * 128);

    final_tc<<<296, 512, FIN_SMEM>>>(node_feats, bf1, g_ln, b_ln, out);
}